// round 1
// baseline (speedup 1.0000x reference)
#include <cuda_runtime.h>
#include <math.h>

// ---------------------------------------------------------------------------
// Problem constants
// ---------------------------------------------------------------------------
#define B_DIM 4
#define T_DIM 2048
#define C_DIM 2048
#define N_HEAD 16
#define N_KV 4
#define HD 128
#define M_TOT (B_DIM * T_DIM)           // 8192
#define ROPE_HALF (HD / 2)              // 64
#define QK_SCALE 0.08838834764831845f   // 1/sqrt(128)

// ---------------------------------------------------------------------------
// Scratch (static device globals -- no allocation allowed)
// ---------------------------------------------------------------------------
__device__ float g_q[(size_t)B_DIM * N_HEAD * T_DIM * HD];   // [B,H,T,D]   64 MB
__device__ float g_k[(size_t)B_DIM * N_KV * T_DIM * HD];     // [B,KV,T,D]  16 MB
__device__ float g_v[(size_t)B_DIM * N_KV * T_DIM * HD];     // [B,KV,T,D]  16 MB
__device__ float g_attn[(size_t)M_TOT * C_DIM];              // [B*T, C]    64 MB

// ---------------------------------------------------------------------------
// Tiled NT GEMM:  out = A[M,K] @ W[N,K]^T
// MODE 0: Q proj  -> RoPE + scale, write g_q as [B,H,T,D]
// MODE 1: K proj  -> RoPE,        write g_k as [B,KV,T,D]
// MODE 2: V proj  ->              write g_v as [B,KV,T,D]
// MODE 3: O proj  -> plain row-major [M, N] (final output)
// ---------------------------------------------------------------------------
template <int MODE>
__global__ __launch_bounds__(256) void gemm_nt(
    const float* __restrict__ A, const float* __restrict__ W,
    float* __restrict__ out, const float* __restrict__ rope,
    int N, int K)
{
    constexpr int BM = 128, BN = 128, BK = 32, PAD = 132;
    __shared__ float As[BK * PAD];   // [k][m]
    __shared__ float Bs[BK * PAD];   // [k][n]

    const int tid = threadIdx.x;
    const int m0 = blockIdx.y * BM;
    const int n0 = blockIdx.x * BN;
    const int ty = tid >> 4;   // 0..15
    const int tx = tid & 15;   // 0..15

    float acc[8][8];
#pragma unroll
    for (int i = 0; i < 8; i++)
#pragma unroll
        for (int j = 0; j < 8; j++) acc[i][j] = 0.f;

    for (int k0 = 0; k0 < K; k0 += BK) {
        // stage A,W tiles transposed into smem (1024 float4 each)
#pragma unroll
        for (int q = 0; q < 4; q++) {
            int idx = tid + q * 256;          // 0..1023
            int r = idx >> 3;                 // 0..127
            int c4 = idx & 7;                 // 0..7
            float4 va = *(const float4*)(A + (size_t)(m0 + r) * K + k0 + c4 * 4);
            As[(c4 * 4 + 0) * PAD + r] = va.x;
            As[(c4 * 4 + 1) * PAD + r] = va.y;
            As[(c4 * 4 + 2) * PAD + r] = va.z;
            As[(c4 * 4 + 3) * PAD + r] = va.w;
            float4 vb = *(const float4*)(W + (size_t)(n0 + r) * K + k0 + c4 * 4);
            Bs[(c4 * 4 + 0) * PAD + r] = vb.x;
            Bs[(c4 * 4 + 1) * PAD + r] = vb.y;
            Bs[(c4 * 4 + 2) * PAD + r] = vb.z;
            Bs[(c4 * 4 + 3) * PAD + r] = vb.w;
        }
        __syncthreads();

#pragma unroll
        for (int kk = 0; kk < BK; kk++) {
            float a[8], b[8];
            *(float4*)(a)     = *(float4*)&As[kk * PAD + ty * 8];
            *(float4*)(a + 4) = *(float4*)&As[kk * PAD + ty * 8 + 4];
            *(float4*)(b)     = *(float4*)&Bs[kk * PAD + tx * 8];
            *(float4*)(b + 4) = *(float4*)&Bs[kk * PAD + tx * 8 + 4];
#pragma unroll
            for (int i = 0; i < 8; i++)
#pragma unroll
                for (int j = 0; j < 8; j++) acc[i][j] += a[i] * b[j];
        }
        __syncthreads();
    }

    // epilogue
#pragma unroll
    for (int i = 0; i < 8; i++) {
        int m = m0 + ty * 8 + i;
        int bb = m >> 11;            // m / T_DIM
        int t  = m & (T_DIM - 1);
        if (MODE == 3) {
#pragma unroll
            for (int j = 0; j < 8; j++) {
                int n = n0 + tx * 8 + j;
                out[(size_t)m * N + n] = acc[i][j];
            }
        } else if (MODE == 2) {
#pragma unroll
            for (int j = 0; j < 8; j++) {
                int n = n0 + tx * 8 + j;
                int kv = n >> 7;
                int d = n & (HD - 1);
                out[(((size_t)bb * N_KV + kv) * T_DIM + t) * HD + d] = acc[i][j];
            }
        } else {
            // RoPE modes (0 = Q, 1 = K). n is even at j even, so (j, j+1) is a pair.
#pragma unroll
            for (int jp = 0; jp < 4; jp++) {
                int j = jp * 2;
                int n = n0 + tx * 8 + j;
                int hh = n >> 7;             // head (Q: 0..15, K: 0..3)
                int d = n & (HD - 1);        // even
                float ang = rope[t * ROPE_HALF + (d >> 1)];
                float sn, cs;
                sincosf(ang, &sn, &cs);      // precise: angles up to ~2047 rad
                float e = acc[i][j], o = acc[i][j + 1];
                float oe = e * cs - o * sn;
                float oo = e * sn + o * cs;
                size_t idx;
                if (MODE == 0) {
                    oe *= QK_SCALE; oo *= QK_SCALE;
                    idx = (((size_t)bb * N_HEAD + hh) * T_DIM + t) * HD + d;
                } else {
                    idx = (((size_t)bb * N_KV + hh) * T_DIM + t) * HD + d;
                }
                out[idx] = oe;
                out[idx + 1] = oo;
            }
        }
    }
}

// ---------------------------------------------------------------------------
// Flash attention: causal + pad mask, online softmax.
// Grid: (T/64, N_HEAD, B). Block: 256 threads.
// Thread (qr = tid>>2, g = tid&3):
//   S phase : computes S[qr][g + 4*jj], jj = 0..15
//   PV phase: accumulates O[qr][ (dd*4+g)*4 .. +3 ] as float4, dd = 0..7
// Smem strides padded (132 / 68) -> every LDS.128 conflict-free.
// q tile pre-scaled by 1/sqrt(D) in the GEMM epilogue.
// ---------------------------------------------------------------------------
#define BQ 64
#define BK_F 64
#define QSTR 132
#define PSTR 68
#define FLASH_SMEM_FLOATS (3 * BQ * QSTR + BQ * PSTR)
#define FLASH_SMEM_BYTES (FLASH_SMEM_FLOATS * 4 + BK_F * 4)

__global__ __launch_bounds__(256) void flash_kernel(
    const int* __restrict__ amask, float* __restrict__ outp)
{
    extern __shared__ float sm[];
    float* Qs = sm;
    float* Ks = Qs + BQ * QSTR;
    float* Vs = Ks + BQ * QSTR;
    float* Ps = Vs + BQ * QSTR;
    int*   Ms = (int*)(Ps + BQ * PSTR);

    const int tid = threadIdx.x;
    const int qt = blockIdx.x;
    const int h  = blockIdx.y;
    const int b  = blockIdx.z;
    const int kvh = h & (N_KV - 1);          // jnp.tile -> h % N_KV

    const float* qbase = g_q + (((size_t)b * N_HEAD + h) * T_DIM + qt * BQ) * HD;
    const float* kbase = g_k + (((size_t)b * N_KV + kvh) * T_DIM) * HD;
    const float* vbase = g_v + (((size_t)b * N_KV + kvh) * T_DIM) * HD;

    // load Q tile (scaled already)
    for (int idx = tid; idx < BQ * 32; idx += 256) {
        int r = idx >> 5, c4 = idx & 31;
        *(float4*)&Qs[r * QSTR + c4 * 4] =
            *(const float4*)(qbase + (size_t)r * HD + c4 * 4);
    }

    const int qr = tid >> 2;
    const int g  = tid & 3;
    const int qg = qt * BQ + qr;

    float m_i = -1e30f, l_i = 0.f;
    float4 o[8];
#pragma unroll
    for (int dd = 0; dd < 8; dd++) o[dd] = make_float4(0.f, 0.f, 0.f, 0.f);

    for (int kt = 0; kt <= qt; kt++) {
        __syncthreads();   // previous PV / Q-load fence before overwriting tiles
        const float* kb = kbase + (size_t)kt * BK_F * HD;
        const float* vb = vbase + (size_t)kt * BK_F * HD;
        for (int idx = tid; idx < BK_F * 32; idx += 256) {
            int r = idx >> 5, c4 = idx & 31;
            *(float4*)&Ks[r * QSTR + c4 * 4] =
                *(const float4*)(kb + (size_t)r * HD + c4 * 4);
            *(float4*)&Vs[r * QSTR + c4 * 4] =
                *(const float4*)(vb + (size_t)r * HD + c4 * 4);
        }
        if (tid < BK_F) Ms[tid] = amask[b * T_DIM + kt * BK_F + tid];
        __syncthreads();

        // ---- S = Q K^T (q pre-scaled) ----
        float s[16];
#pragma unroll
        for (int jj = 0; jj < 16; jj++) s[jj] = 0.f;
#pragma unroll
        for (int d4 = 0; d4 < 32; d4++) {
            float4 qv = *(float4*)&Qs[qr * QSTR + d4 * 4];
#pragma unroll
            for (int jj = 0; jj < 16; jj++) {
                float4 kv = *(float4*)&Ks[(g + jj * 4) * QSTR + d4 * 4];
                s[jj] += qv.x * kv.x + qv.y * kv.y + qv.z * kv.z + qv.w * kv.w;
            }
        }

        // ---- mask + row max ----
        float tmax = -1e30f;
#pragma unroll
        for (int jj = 0; jj < 16; jj++) {
            int kc = g + jj * 4;
            int kg = kt * BK_F + kc;
            bool ok = (kg <= qg) && (Ms[kc] != 0);
            s[jj] = ok ? s[jj] : -1e30f;
            tmax = fmaxf(tmax, s[jj]);
        }
        tmax = fmaxf(tmax, __shfl_xor_sync(0xffffffffu, tmax, 1));
        tmax = fmaxf(tmax, __shfl_xor_sync(0xffffffffu, tmax, 2));
        float m_new = fmaxf(m_i, tmax);
        float alpha = __expf(m_i - m_new);

        // ---- P = exp(S - m), row sum ----
        float rsum = 0.f;
#pragma unroll
        for (int jj = 0; jj < 16; jj++) {
            float p = __expf(s[jj] - m_new);
            Ps[qr * PSTR + g + jj * 4] = p;
            rsum += p;
        }
        rsum += __shfl_xor_sync(0xffffffffu, rsum, 1);
        rsum += __shfl_xor_sync(0xffffffffu, rsum, 2);
        l_i = l_i * alpha + rsum;
        m_i = m_new;
        __syncthreads();   // Ps visible to all 4 lanes per row

        // ---- O = alpha*O + P V ----
#pragma unroll
        for (int dd = 0; dd < 8; dd++) {
            o[dd].x *= alpha; o[dd].y *= alpha; o[dd].z *= alpha; o[dd].w *= alpha;
        }
#pragma unroll 4
        for (int k = 0; k < BK_F; k++) {
            float p = Ps[qr * PSTR + k];
#pragma unroll
            for (int dd = 0; dd < 8; dd++) {
                float4 v = *(float4*)&Vs[k * QSTR + (dd * 4 + g) * 4];
                o[dd].x += p * v.x; o[dd].y += p * v.y;
                o[dd].z += p * v.z; o[dd].w += p * v.w;
            }
        }
    }

    float inv = 1.f / l_i;
    float* orow = outp + ((size_t)b * T_DIM + qg) * C_DIM + h * HD;
#pragma unroll
    for (int dd = 0; dd < 8; dd++) {
        float4 w = o[dd];
        w.x *= inv; w.y *= inv; w.z *= inv; w.w *= inv;
        *(float4*)&orow[(dd * 4 + g) * 4] = w;
    }
}

// ---------------------------------------------------------------------------
// Launch
// ---------------------------------------------------------------------------
extern "C" void kernel_launch(void* const* d_in, const int* in_sizes, int n_in,
                              void* d_out, int out_size)
{
    const float* x    = (const float*)d_in[0];
    const float* rope = (const float*)d_in[1];
    const int*   amask= (const int*)  d_in[2];
    const float* Wq   = (const float*)d_in[3];
    const float* Wk   = (const float*)d_in[4];
    const float* Wv   = (const float*)d_in[5];
    const float* Wo   = (const float*)d_in[6];
    float* out = (float*)d_out;

    float *qp, *kp, *vp, *ap;
    cudaGetSymbolAddress((void**)&qp, g_q);
    cudaGetSymbolAddress((void**)&kp, g_k);
    cudaGetSymbolAddress((void**)&vp, g_v);
    cudaGetSymbolAddress((void**)&ap, g_attn);

    cudaFuncSetAttribute(flash_kernel,
                         cudaFuncAttributeMaxDynamicSharedMemorySize,
                         FLASH_SMEM_BYTES);

    dim3 blk(256);
    gemm_nt<0><<<dim3(C_DIM / 128, M_TOT / 128), blk>>>(x, Wq, qp, rope, C_DIM, C_DIM);
    gemm_nt<1><<<dim3((N_KV * HD) / 128, M_TOT / 128), blk>>>(x, Wk, kp, rope, N_KV * HD, C_DIM);
    gemm_nt<2><<<dim3((N_KV * HD) / 128, M_TOT / 128), blk>>>(x, Wv, vp, rope, N_KV * HD, C_DIM);

    flash_kernel<<<dim3(T_DIM / BQ, N_HEAD, B_DIM), 256, FLASH_SMEM_BYTES>>>(amask, ap);

    gemm_nt<3><<<dim3(C_DIM / 128, M_TOT / 128), blk>>>(ap, Wo, out, rope, C_DIM, C_DIM);
}

// round 4
// speedup vs baseline: 2.1131x; 2.1131x over previous
#include <cuda_runtime.h>
#include <cuda_bf16.h>
#include <math.h>
#include <cstdint>

// ---------------------------------------------------------------------------
// Problem constants
// ---------------------------------------------------------------------------
#define B_DIM 4
#define T_DIM 2048
#define C_DIM 2048
#define N_HEAD 16
#define N_KV 4
#define HD 128
#define M_TOT (B_DIM * T_DIM)           // 8192
#define K_DIM 2048
#define NKV_C (N_KV * HD)               // 512
#define QK_SCALE 0.08838834764831845f   // 1/sqrt(128)

// ---------------------------------------------------------------------------
// Scratch (static device globals -- no allocation allowed)
// ---------------------------------------------------------------------------
__device__ float g_q[(size_t)B_DIM * N_HEAD * T_DIM * HD];   // [B,H,T,D]
__device__ float g_k[(size_t)B_DIM * N_KV * T_DIM * HD];
__device__ float g_v[(size_t)B_DIM * N_KV * T_DIM * HD];
__device__ float g_attn[(size_t)M_TOT * C_DIM];

__device__ __nv_bfloat16 g_xhi[(size_t)M_TOT * K_DIM];
__device__ __nv_bfloat16 g_xlo[(size_t)M_TOT * K_DIM];
__device__ __nv_bfloat16 g_ahi[(size_t)M_TOT * K_DIM];
__device__ __nv_bfloat16 g_alo[(size_t)M_TOT * K_DIM];
__device__ __nv_bfloat16 g_wqh[(size_t)C_DIM * K_DIM];
__device__ __nv_bfloat16 g_wql[(size_t)C_DIM * K_DIM];
__device__ __nv_bfloat16 g_wkh[(size_t)NKV_C * K_DIM];
__device__ __nv_bfloat16 g_wkl[(size_t)NKV_C * K_DIM];
__device__ __nv_bfloat16 g_wvh[(size_t)NKV_C * K_DIM];
__device__ __nv_bfloat16 g_wvl[(size_t)NKV_C * K_DIM];
__device__ __nv_bfloat16 g_woh[(size_t)C_DIM * K_DIM];
__device__ __nv_bfloat16 g_wol[(size_t)C_DIM * K_DIM];
__device__ float g_cos[(size_t)T_DIM * 64];
__device__ float g_sin[(size_t)T_DIM * 64];

// ---------------------------------------------------------------------------
// Helpers (sm_100-safe: mma.sync / ldmatrix / cp.async only)
// ---------------------------------------------------------------------------
__device__ __forceinline__ uint32_t smem_u32(const void* p) {
    uint32_t a;
    asm("{ .reg .u64 t; cvta.to.shared.u64 t, %1; cvt.u32.u64 %0, t; }"
        : "=r"(a) : "l"(p));
    return a;
}
__device__ __forceinline__ void cp_async16(uint32_t dst, const void* src) {
    asm volatile("cp.async.cg.shared.global [%0], [%1], 16;" :: "r"(dst), "l"(src));
}
__device__ __forceinline__ void cp_commit() {
    asm volatile("cp.async.commit_group;" ::: "memory");
}
__device__ __forceinline__ void cp_wait1() {
    asm volatile("cp.async.wait_group 1;" ::: "memory");
}
__device__ __forceinline__ void cp_wait0() {
    asm volatile("cp.async.wait_group 0;" ::: "memory");
}
__device__ __forceinline__ void ldsm4(uint32_t& r0, uint32_t& r1, uint32_t& r2,
                                      uint32_t& r3, uint32_t addr) {
    asm volatile("ldmatrix.sync.aligned.m8n8.x4.shared.b16 {%0,%1,%2,%3}, [%4];"
                 : "=r"(r0), "=r"(r1), "=r"(r2), "=r"(r3) : "r"(addr));
}
__device__ __forceinline__ void mma16816(float* d, const uint32_t* a,
                                         uint32_t b0, uint32_t b1) {
    asm volatile(
        "mma.sync.aligned.m16n8k16.row.col.f32.bf16.bf16.f32 "
        "{%0,%1,%2,%3}, {%4,%5,%6,%7}, {%8,%9}, {%0,%1,%2,%3};"
        : "+f"(d[0]), "+f"(d[1]), "+f"(d[2]), "+f"(d[3])
        : "r"(a[0]), "r"(a[1]), "r"(a[2]), "r"(a[3]), "r"(b0), "r"(b1));
}

// ---------------------------------------------------------------------------
// Prep kernels
// ---------------------------------------------------------------------------
__global__ void rope_tables_kernel(const float* __restrict__ rope) {
    int i = blockIdx.x * 256 + threadIdx.x;
    if (i < T_DIM * 64) {
        float sn, cs;
        sincosf(rope[i], &sn, &cs);
        g_sin[i] = sn; g_cos[i] = cs;
    }
}

__global__ void to_bf16_pair(const float* __restrict__ src,
                             __nv_bfloat16* __restrict__ hi,
                             __nv_bfloat16* __restrict__ lo, int n4) {
    int i = blockIdx.x * 256 + threadIdx.x;
    if (i >= n4) return;
    float4 v = ((const float4*)src)[i];
    __nv_bfloat16 h0 = __float2bfloat16(v.x), h1 = __float2bfloat16(v.y);
    __nv_bfloat16 h2 = __float2bfloat16(v.z), h3 = __float2bfloat16(v.w);
    __nv_bfloat16 l0 = __float2bfloat16(v.x - __bfloat162float(h0));
    __nv_bfloat16 l1 = __float2bfloat16(v.y - __bfloat162float(h1));
    __nv_bfloat16 l2 = __float2bfloat16(v.z - __bfloat162float(h2));
    __nv_bfloat16 l3 = __float2bfloat16(v.w - __bfloat162float(h3));
    ((__nv_bfloat162*)hi)[2 * i]     = __nv_bfloat162(h0, h1);
    ((__nv_bfloat162*)hi)[2 * i + 1] = __nv_bfloat162(h2, h3);
    ((__nv_bfloat162*)lo)[2 * i]     = __nv_bfloat162(l0, l1);
    ((__nv_bfloat162*)lo)[2 * i + 1] = __nv_bfloat162(l2, l3);
}

// ---------------------------------------------------------------------------
// mma.sync bf16x3 NT GEMM: out = A[M,K] @ W[N,K]^T (fp32-accurate)
// 128x128 tile/CTA, BK=32, 256 threads = 8 warps (2x4), warp tile 64x32.
// K_eff = 3*K via pointer passes: (Ahi,Bhi), (Ahi,Blo), (Alo,Bhi).
// MODE 0: Q proj -> RoPE+scale, [B,H,T,D]; 1: K proj -> RoPE, [B,KV,T,D];
// MODE 2: V proj -> [B,KV,T,D]; 3: O proj -> row-major [M,N].
// ---------------------------------------------------------------------------
#define GSTR 40            // smem row stride in bf16 (80B): ldmatrix conflict-free
#define TILE_B (128 * GSTR * 2)   // 10240 bytes per operand tile

template <int MODE>
__global__ __launch_bounds__(256)
void gemm_mma(const __nv_bfloat16* __restrict__ Ahi, const __nv_bfloat16* __restrict__ Alo,
              const __nv_bfloat16* __restrict__ Bhi, const __nv_bfloat16* __restrict__ Blo,
              float* __restrict__ out, int N)
{
    __shared__ __align__(16) char smem[2 * 2 * TILE_B];   // 2 stages x (A,B)
    const uint32_t sb = smem_u32(smem);

    const int tid = threadIdx.x;
    const int lane = tid & 31;
    const int wid = tid >> 5;
    const int wm = wid >> 2;          // 0..1  (64-row slab)
    const int wn = wid & 3;           // 0..3  (32-col slab)
    const int m0 = blockIdx.y * 128, n0 = blockIdx.x * 128;

    const __nv_bfloat16* Ap[3] = { Ahi, Ahi, Alo };
    const __nv_bfloat16* Bp[3] = { Bhi, Blo, Bhi };

    const int NCH = K_DIM / 32;       // 64 chunks per pass
    const int NTOT = 3 * NCH;         // 192

    // cp.async staging: 1024 16B lines per chunk (A:512, B:512), 4 per thread
    auto load_chunk = [&](int c) {
        int pass = c / NCH;
        int k0 = (c - pass * NCH) * 32;
        uint32_t st = sb + (uint32_t)(c & 1) * (2 * TILE_B);
        const __nv_bfloat16* As = Ap[pass] + (size_t)m0 * K_DIM + k0;
        const __nv_bfloat16* Bs = Bp[pass] + (size_t)n0 * K_DIM + k0;
#pragma unroll
        for (int i = 0; i < 4; i++) {
            int idx = tid + i * 256;          // 0..1023
            int rem = idx & 511;
            int r = rem >> 2, c4 = rem & 3;
            const __nv_bfloat16* src = (idx < 512)
                ? (As + (size_t)r * K_DIM + c4 * 8)
                : (Bs + (size_t)r * K_DIM + c4 * 8);
            uint32_t dst = st + (uint32_t)((idx < 512) ? 0 : TILE_B)
                         + (uint32_t)(r * (GSTR * 2) + c4 * 16);
            cp_async16(dst, src);
        }
        cp_commit();
    };

    float acc[4][4][4];
#pragma unroll
    for (int mi = 0; mi < 4; mi++)
#pragma unroll
        for (int nf = 0; nf < 4; nf++)
#pragma unroll
            for (int e = 0; e < 4; e++) acc[mi][nf][e] = 0.f;

    // ldmatrix lane address components (constant per thread)
    const int a_row = lane & 15;                       // + wm*64 + mi*16
    const int a_col8 = (lane >> 4) * 8;                // + s*16
    const int b_row = (lane & 7) + ((lane & 16) >> 1); // + wn*32 + nj*16
    const int b_col8 = (lane & 8);                     // + s*16

    load_chunk(0);

    for (int c = 0; c < NTOT; c++) {
        if (c + 1 < NTOT) { load_chunk(c + 1); cp_wait1(); }
        else              { cp_wait0(); }
        __syncthreads();

        uint32_t st = sb + (uint32_t)(c & 1) * (2 * TILE_B);
        uint32_t aBase = st;
        uint32_t bBase = st + TILE_B;

#pragma unroll
        for (int s = 0; s < 2; s++) {
            uint32_t a[4][4];
#pragma unroll
            for (int mi = 0; mi < 4; mi++) {
                uint32_t addr = aBase + (uint32_t)(
                    (wm * 64 + mi * 16 + a_row) * (GSTR * 2)
                    + (s * 16 + a_col8) * 2);
                ldsm4(a[mi][0], a[mi][1], a[mi][2], a[mi][3], addr);
            }
            uint32_t b[2][4];
#pragma unroll
            for (int nj = 0; nj < 2; nj++) {
                uint32_t addr = bBase + (uint32_t)(
                    (wn * 32 + nj * 16 + b_row) * (GSTR * 2)
                    + (s * 16 + b_col8) * 2);
                ldsm4(b[nj][0], b[nj][1], b[nj][2], b[nj][3], addr);
            }
#pragma unroll
            for (int mi = 0; mi < 4; mi++)
#pragma unroll
                for (int nf = 0; nf < 4; nf++)
                    mma16816(acc[mi][nf], a[mi],
                             b[nf >> 1][(nf & 1) * 2], b[nf >> 1][(nf & 1) * 2 + 1]);
        }
        __syncthreads();
    }

    // ------------------- epilogue (registers -> gmem) -------------------
    // acc[mi][nf]: c0=(r,col) c1=(r,col+1) c2=(r+8,col) c3=(r+8,col+1)
    // r = wm*64 + mi*16 + lane/4 ; col = wn*32 + nf*8 + (lane%4)*2
#pragma unroll
    for (int mi = 0; mi < 4; mi++) {
        int r_loc = wm * 64 + mi * 16 + (lane >> 2);
#pragma unroll
        for (int half = 0; half < 2; half++) {
            int mr = m0 + r_loc + half * 8;
            int bb = mr >> 11;
            int t  = mr & (T_DIM - 1);
#pragma unroll
            for (int nf = 0; nf < 4; nf++) {
                int lc = wn * 32 + nf * 8 + (lane & 3) * 2;   // local col (0..127)
                float e = acc[mi][nf][half * 2];
                float o = acc[mi][nf][half * 2 + 1];
                if (MODE == 3) {
                    int n = n0 + lc;
                    *(float2*)&out[(size_t)mr * N + n] = make_float2(e, o);
                } else if (MODE == 2) {
                    int n = n0 + lc;
                    int kv = n >> 7, d = n & (HD - 1);
                    *(float2*)&out[(((size_t)bb * N_KV + kv) * T_DIM + t) * HD + d]
                        = make_float2(e, o);
                } else {
                    // RoPE: (e,o) is an even/odd pair; lc<128, head from n0+lc.
                    int n = n0 + lc;
                    int hh = n >> 7, d = n & (HD - 1);
                    float cs = g_cos[t * 64 + (d >> 1)];
                    float sn = g_sin[t * 64 + (d >> 1)];
                    float oe = e * cs - o * sn;
                    float oo = e * sn + o * cs;
                    size_t idx;
                    if (MODE == 0) {
                        oe *= QK_SCALE; oo *= QK_SCALE;
                        idx = (((size_t)bb * N_HEAD + hh) * T_DIM + t) * HD + d;
                    } else {
                        idx = (((size_t)bb * N_KV + hh) * T_DIM + t) * HD + d;
                    }
                    *(float2*)&out[idx] = make_float2(oe, oo);
                }
            }
        }
    }
}

// ---------------------------------------------------------------------------
// Flash attention v2 (fp32 SIMT, 4x8 register blocking)
// BQ=128, BK=64, 256 threads. Thread (rg=tid>>3 rows rg*4..+3, cg=tid&7).
// ---------------------------------------------------------------------------
#define BQ 128
#define BKF 64
#define QSTR 132
#define PSTR 68
#define FL_SMEM ((BQ * QSTR + 2 * BKF * QSTR + BQ * PSTR) * 4 + BKF * 4)

__global__ __launch_bounds__(256) void flash_v2(
    const int* __restrict__ amask, float* __restrict__ outp)
{
    extern __shared__ float sm[];
    float* Qs = sm;
    float* Ks = Qs + BQ * QSTR;
    float* Vs = Ks + BKF * QSTR;
    float* Ps = Vs + BKF * QSTR;
    int*   Ms = (int*)(Ps + BQ * PSTR);

    const int tid = threadIdx.x;
    const int qt = blockIdx.x;
    const int h  = blockIdx.y;
    const int b  = blockIdx.z;
    const int kvh = h & (N_KV - 1);

    const float* qb = g_q + (((size_t)b * N_HEAD + h) * T_DIM + qt * BQ) * HD;
    const float* kbase = g_k + (((size_t)b * N_KV + kvh) * T_DIM) * HD;
    const float* vbase = g_v + (((size_t)b * N_KV + kvh) * T_DIM) * HD;

    for (int idx = tid; idx < BQ * 32; idx += 256) {
        int r = idx >> 5, c4 = idx & 31;
        *(float4*)&Qs[r * QSTR + c4 * 4] = *(const float4*)(qb + (size_t)r * HD + c4 * 4);
    }

    const int rg = tid >> 3;
    const int cg = tid & 7;
    const int qg0 = qt * BQ + rg * 4;

    float m_i[4], l_i[4];
    float4 o[4][4];
#pragma unroll
    for (int i = 0; i < 4; i++) {
        m_i[i] = -1e30f; l_i[i] = 0.f;
#pragma unroll
        for (int jj = 0; jj < 4; jj++) o[i][jj] = make_float4(0.f, 0.f, 0.f, 0.f);
    }

    const int nkt = 2 * qt + 2;
    for (int kt = 0; kt < nkt; kt++) {
        __syncthreads();
        const float* kb = kbase + (size_t)kt * BKF * HD;
        const float* vb = vbase + (size_t)kt * BKF * HD;
        for (int idx = tid; idx < BKF * 32; idx += 256) {
            int r = idx >> 5, c4 = idx & 31;
            *(float4*)&Ks[r * QSTR + c4 * 4] = *(const float4*)(kb + (size_t)r * HD + c4 * 4);
            *(float4*)&Vs[r * QSTR + c4 * 4] = *(const float4*)(vb + (size_t)r * HD + c4 * 4);
        }
        if (tid < BKF) Ms[tid] = amask[b * T_DIM + kt * BKF + tid];
        __syncthreads();

        // ---- S = Q K^T : 4 rows x 8 cols per thread ----
        float s[4][8];
#pragma unroll
        for (int i = 0; i < 4; i++)
#pragma unroll
            for (int j = 0; j < 8; j++) s[i][j] = 0.f;

#pragma unroll 8
        for (int d4 = 0; d4 < 32; d4++) {
            float4 q[4], k[8];
#pragma unroll
            for (int i = 0; i < 4; i++)
                q[i] = *(float4*)&Qs[(rg * 4 + i) * QSTR + d4 * 4];
#pragma unroll
            for (int j = 0; j < 8; j++)
                k[j] = *(float4*)&Ks[(j * 8 + cg) * QSTR + d4 * 4];
#pragma unroll
            for (int i = 0; i < 4; i++)
#pragma unroll
                for (int j = 0; j < 8; j++)
                    s[i][j] += q[i].x * k[j].x + q[i].y * k[j].y
                             + q[i].z * k[j].z + q[i].w * k[j].w;
        }

        // ---- mask, online softmax (per row i; 8 lanes per row) ----
        float alpha[4];
#pragma unroll
        for (int i = 0; i < 4; i++) {
            float tmax = -1e30f;
#pragma unroll
            for (int j = 0; j < 8; j++) {
                int kc = j * 8 + cg;
                int kg = kt * BKF + kc;
                bool ok = (kg <= qg0 + i) && (Ms[kc] != 0);
                s[i][j] = ok ? s[i][j] : -1e30f;
                tmax = fmaxf(tmax, s[i][j]);
            }
            tmax = fmaxf(tmax, __shfl_xor_sync(0xffffffffu, tmax, 1));
            tmax = fmaxf(tmax, __shfl_xor_sync(0xffffffffu, tmax, 2));
            tmax = fmaxf(tmax, __shfl_xor_sync(0xffffffffu, tmax, 4));
            float mn = fmaxf(m_i[i], tmax);
            float al = __expf(m_i[i] - mn);
            float rs = 0.f;
#pragma unroll
            for (int j = 0; j < 8; j++) {
                float p = __expf(s[i][j] - mn);
                Ps[(rg * 4 + i) * PSTR + j * 8 + cg] = p;
                rs += p;
            }
            rs += __shfl_xor_sync(0xffffffffu, rs, 1);
            rs += __shfl_xor_sync(0xffffffffu, rs, 2);
            rs += __shfl_xor_sync(0xffffffffu, rs, 4);
            l_i[i] = l_i[i] * al + rs;
            m_i[i] = mn;
            alpha[i] = al;
        }
        __syncthreads();

        // ---- O = alpha*O + P V ----
#pragma unroll
        for (int i = 0; i < 4; i++) {
            float a = alpha[i];
#pragma unroll
            for (int jj = 0; jj < 4; jj++) {
                o[i][jj].x *= a; o[i][jj].y *= a; o[i][jj].z *= a; o[i][jj].w *= a;
            }
        }
#pragma unroll 4
        for (int k4 = 0; k4 < 16; k4++) {
            float4 p4[4];
#pragma unroll
            for (int i = 0; i < 4; i++)
                p4[i] = *(float4*)&Ps[(rg * 4 + i) * PSTR + k4 * 4];
#pragma unroll
            for (int kk = 0; kk < 4; kk++) {
                float4 v[4];
#pragma unroll
                for (int jj = 0; jj < 4; jj++)
                    v[jj] = *(float4*)&Vs[(k4 * 4 + kk) * QSTR + cg * 4 + jj * 32];
#pragma unroll
                for (int i = 0; i < 4; i++) {
                    float pk = (kk == 0) ? p4[i].x : (kk == 1) ? p4[i].y
                             : (kk == 2) ? p4[i].z : p4[i].w;
#pragma unroll
                    for (int jj = 0; jj < 4; jj++) {
                        o[i][jj].x += pk * v[jj].x; o[i][jj].y += pk * v[jj].y;
                        o[i][jj].z += pk * v[jj].z; o[i][jj].w += pk * v[jj].w;
                    }
                }
            }
        }
    }

#pragma unroll
    for (int i = 0; i < 4; i++) {
        float inv = 1.f / l_i[i];
        float* orow = outp + ((size_t)b * T_DIM + qg0 + i) * C_DIM + h * HD;
#pragma unroll
        for (int jj = 0; jj < 4; jj++) {
            float4 w = o[i][jj];
            w.x *= inv; w.y *= inv; w.z *= inv; w.w *= inv;
            *(float4*)&orow[cg * 4 + jj * 32] = w;
        }
    }
}

// ---------------------------------------------------------------------------
// Launch
// ---------------------------------------------------------------------------
extern "C" void kernel_launch(void* const* d_in, const int* in_sizes, int n_in,
                              void* d_out, int out_size)
{
    const float* x    = (const float*)d_in[0];
    const float* rope = (const float*)d_in[1];
    const int*   am   = (const int*)  d_in[2];
    const float* Wq   = (const float*)d_in[3];
    const float* Wk   = (const float*)d_in[4];
    const float* Wv   = (const float*)d_in[5];
    const float* Wo   = (const float*)d_in[6];
    float* out = (float*)d_out;

    float *qp, *kp, *vp, *ap;
    cudaGetSymbolAddress((void**)&qp, g_q);
    cudaGetSymbolAddress((void**)&kp, g_k);
    cudaGetSymbolAddress((void**)&vp, g_v);
    cudaGetSymbolAddress((void**)&ap, g_attn);
    __nv_bfloat16 *xh, *xl, *ah, *al, *wqh, *wql, *wkh, *wkl, *wvh, *wvl, *woh, *wol;
    cudaGetSymbolAddress((void**)&xh, g_xhi);  cudaGetSymbolAddress((void**)&xl, g_xlo);
    cudaGetSymbolAddress((void**)&ah, g_ahi);  cudaGetSymbolAddress((void**)&al, g_alo);
    cudaGetSymbolAddress((void**)&wqh, g_wqh); cudaGetSymbolAddress((void**)&wql, g_wql);
    cudaGetSymbolAddress((void**)&wkh, g_wkh); cudaGetSymbolAddress((void**)&wkl, g_wkl);
    cudaGetSymbolAddress((void**)&wvh, g_wvh); cudaGetSymbolAddress((void**)&wvl, g_wvl);
    cudaGetSymbolAddress((void**)&woh, g_woh); cudaGetSymbolAddress((void**)&wol, g_wol);

    cudaFuncSetAttribute(flash_v2, cudaFuncAttributeMaxDynamicSharedMemorySize, FL_SMEM);

    // prep: rope tables + bf16 hi/lo splits
    rope_tables_kernel<<<(T_DIM * 64 + 255) / 256, 256>>>(rope);
    to_bf16_pair<<<(M_TOT * K_DIM / 4 + 255) / 256, 256>>>(x, xh, xl, M_TOT * K_DIM / 4);
    to_bf16_pair<<<(C_DIM * K_DIM / 4 + 255) / 256, 256>>>(Wq, wqh, wql, C_DIM * K_DIM / 4);
    to_bf16_pair<<<(NKV_C * K_DIM / 4 + 255) / 256, 256>>>(Wk, wkh, wkl, NKV_C * K_DIM / 4);
    to_bf16_pair<<<(NKV_C * K_DIM / 4 + 255) / 256, 256>>>(Wv, wvh, wvl, NKV_C * K_DIM / 4);
    to_bf16_pair<<<(C_DIM * K_DIM / 4 + 255) / 256, 256>>>(Wo, woh, wol, C_DIM * K_DIM / 4);

    // projections (mma.sync tensor cores)
    gemm_mma<0><<<dim3(C_DIM / 128, M_TOT / 128), 256>>>(xh, xl, wqh, wql, qp, C_DIM);
    gemm_mma<1><<<dim3(NKV_C / 128, M_TOT / 128), 256>>>(xh, xl, wkh, wkl, kp, NKV_C);
    gemm_mma<2><<<dim3(NKV_C / 128, M_TOT / 128), 256>>>(xh, xl, wvh, wvl, vp, NKV_C);

    // attention
    flash_v2<<<dim3(T_DIM / BQ, N_HEAD, B_DIM), 256, FL_SMEM>>>(am, ap);

    // output projection
    to_bf16_pair<<<(M_TOT * K_DIM / 4 + 255) / 256, 256>>>(ap, ah, al, M_TOT * K_DIM / 4);
    gemm_mma<3><<<dim3(C_DIM / 128, M_TOT / 128), 256>>>(ah, al, woh, wol, out, C_DIM);
}

// round 6
// speedup vs baseline: 5.5824x; 2.6418x over previous
#include <cuda_runtime.h>
#include <cuda_bf16.h>
#include <cuda_fp16.h>
#include <math.h>
#include <cstdint>

// ---------------------------------------------------------------------------
#define B_DIM 4
#define T_DIM 2048
#define C_DIM 2048
#define N_HEAD 16
#define N_KV 4
#define HD 128
#define M_TOT (B_DIM * T_DIM)           // 8192
#define K_DIM 2048
#define NKV_C (N_KV * HD)               // 512
#define QK_SCALE 0.08838834764831845f   // 1/sqrt(128)
#define LOG2E 1.4426950408889634f

// ---------------------------------------------------------------------------
// Scratch (static device globals)
// ---------------------------------------------------------------------------
__device__ __half g_xh[(size_t)M_TOT * K_DIM];
__device__ __half g_wq16[(size_t)C_DIM * K_DIM];
__device__ __half g_wk16[(size_t)NKV_C * K_DIM];
__device__ __half g_wv16[(size_t)NKV_C * K_DIM];
__device__ __half g_qh[(size_t)B_DIM * N_HEAD * T_DIM * HD];  // [B,H,T,D]
__device__ __half g_kh[(size_t)B_DIM * N_KV * T_DIM * HD];
__device__ __half g_vh[(size_t)B_DIM * N_KV * T_DIM * HD];
__device__ __nv_bfloat16 g_ahi[(size_t)M_TOT * C_DIM];        // attn out hi
__device__ __nv_bfloat16 g_alo[(size_t)M_TOT * C_DIM];        // attn out lo
__device__ __nv_bfloat16 g_woh[(size_t)C_DIM * K_DIM];
__device__ __nv_bfloat16 g_wol[(size_t)C_DIM * K_DIM];
__device__ float g_cos[(size_t)T_DIM * 64];
__device__ float g_sin[(size_t)T_DIM * 64];

// ---------------------------------------------------------------------------
// Helpers (sm_100-safe)
// ---------------------------------------------------------------------------
__device__ __forceinline__ uint32_t smem_u32(const void* p) {
    uint32_t a;
    asm("{ .reg .u64 t; cvta.to.shared.u64 t, %1; cvt.u32.u64 %0, t; }"
        : "=r"(a) : "l"(p));
    return a;
}
__device__ __forceinline__ void cp_async16(uint32_t dst, const void* src) {
    asm volatile("cp.async.cg.shared.global [%0], [%1], 16;" :: "r"(dst), "l"(src));
}
__device__ __forceinline__ void cp_commit() {
    asm volatile("cp.async.commit_group;" ::: "memory");
}
__device__ __forceinline__ void cp_wait1() {
    asm volatile("cp.async.wait_group 1;" ::: "memory");
}
__device__ __forceinline__ void cp_wait0() {
    asm volatile("cp.async.wait_group 0;" ::: "memory");
}
__device__ __forceinline__ void ldsm4(uint32_t& r0, uint32_t& r1, uint32_t& r2,
                                      uint32_t& r3, uint32_t addr) {
    asm volatile("ldmatrix.sync.aligned.m8n8.x4.shared.b16 {%0,%1,%2,%3}, [%4];"
                 : "=r"(r0), "=r"(r1), "=r"(r2), "=r"(r3) : "r"(addr));
}
__device__ __forceinline__ void ldsm4t(uint32_t& r0, uint32_t& r1, uint32_t& r2,
                                       uint32_t& r3, uint32_t addr) {
    asm volatile("ldmatrix.sync.aligned.m8n8.x4.trans.shared.b16 {%0,%1,%2,%3}, [%4];"
                 : "=r"(r0), "=r"(r1), "=r"(r2), "=r"(r3) : "r"(addr));
}
__device__ __forceinline__ void mma_bf16(float* d, const uint32_t* a,
                                         uint32_t b0, uint32_t b1) {
    asm volatile(
        "mma.sync.aligned.m16n8k16.row.col.f32.bf16.bf16.f32 "
        "{%0,%1,%2,%3}, {%4,%5,%6,%7}, {%8,%9}, {%0,%1,%2,%3};"
        : "+f"(d[0]), "+f"(d[1]), "+f"(d[2]), "+f"(d[3])
        : "r"(a[0]), "r"(a[1]), "r"(a[2]), "r"(a[3]), "r"(b0), "r"(b1));
}
__device__ __forceinline__ void mma_f16(float* d, const uint32_t* a,
                                        uint32_t b0, uint32_t b1) {
    asm volatile(
        "mma.sync.aligned.m16n8k16.row.col.f32.f16.f16.f32 "
        "{%0,%1,%2,%3}, {%4,%5,%6,%7}, {%8,%9}, {%0,%1,%2,%3};"
        : "+f"(d[0]), "+f"(d[1]), "+f"(d[2]), "+f"(d[3])
        : "r"(a[0]), "r"(a[1]), "r"(a[2]), "r"(a[3]), "r"(b0), "r"(b1));
}
// fast exp2: degree-5 poly, FFMA pipe only (no MUFU)
__device__ __forceinline__ float exp2p(float x) {
    x = fmaxf(x, -126.f);
    float t = rintf(x);
    float f = x - t;
    float p = 0.0013333558f;
    p = fmaf(p, f, 0.0096181291f);
    p = fmaf(p, f, 0.0555041087f);
    p = fmaf(p, f, 0.2402265070f);
    p = fmaf(p, f, 0.6931471806f);
    p = fmaf(p, f, 1.0f);
    return __int_as_float(__float_as_int(p) + (((int)t) << 23));
}
__device__ __forceinline__ uint32_t pack_h2(float x, float y) {
    __half2 h = __floats2half2_rn(x, y);
    return *(uint32_t*)&h;
}

// ---------------------------------------------------------------------------
// Prep kernels
// ---------------------------------------------------------------------------
__global__ void rope_tables_kernel(const float* __restrict__ rope) {
    int i = blockIdx.x * 256 + threadIdx.x;
    if (i < T_DIM * 64) {
        float sn, cs;
        sincosf(rope[i], &sn, &cs);
        g_sin[i] = sn; g_cos[i] = cs;
    }
}

__global__ void to_f16(const float* __restrict__ src, __half* __restrict__ dst, int n8) {
    int i = blockIdx.x * 256 + threadIdx.x;
    if (i >= n8) return;
    const float4* s4 = (const float4*)src;
    float4 a = s4[2 * i], b = s4[2 * i + 1];
    __half2 h0 = __floats2half2_rn(a.x, a.y);
    __half2 h1 = __floats2half2_rn(a.z, a.w);
    __half2 h2 = __floats2half2_rn(b.x, b.y);
    __half2 h3 = __floats2half2_rn(b.z, b.w);
    uint4 u;
    u.x = *(uint32_t*)&h0; u.y = *(uint32_t*)&h1;
    u.z = *(uint32_t*)&h2; u.w = *(uint32_t*)&h3;
    ((uint4*)dst)[i] = u;
}

__global__ void to_bf16_pair(const float* __restrict__ src,
                             __nv_bfloat16* __restrict__ hi,
                             __nv_bfloat16* __restrict__ lo, int n8) {
    int i = blockIdx.x * 256 + threadIdx.x;
    if (i >= n8) return;
    const float4* s4 = (const float4*)src;
    float4 a = s4[2 * i], b = s4[2 * i + 1];
    float v[8] = {a.x, a.y, a.z, a.w, b.x, b.y, b.z, b.w};
    uint32_t uh[4], ul[4];
#pragma unroll
    for (int j = 0; j < 4; j++) {
        __nv_bfloat16 h0 = __float2bfloat16(v[2 * j]);
        __nv_bfloat16 h1 = __float2bfloat16(v[2 * j + 1]);
        __nv_bfloat162 hh(h0, h1);
        __nv_bfloat162 ll(__float2bfloat16(v[2 * j] - __bfloat162float(h0)),
                          __float2bfloat16(v[2 * j + 1] - __bfloat162float(h1)));
        uh[j] = *(uint32_t*)&hh; ul[j] = *(uint32_t*)&ll;
    }
    ((uint4*)hi)[i] = make_uint4(uh[0], uh[1], uh[2], uh[3]);
    ((uint4*)lo)[i] = make_uint4(ul[0], ul[1], ul[2], ul[3]);
}

// ---------------------------------------------------------------------------
// fp16 single-pass NT GEMM: out = A[M,K] @ W[N,K]^T, fp32 accum.
// 128x128 tile/CTA, BK=32, 256 threads, warp tile 64x32. Outputs __half.
// MODE 0: Q proj -> RoPE+scale, [B,H,T,D]; 1: K proj -> RoPE, [B,KV,T,D];
// MODE 2: V proj -> [B,KV,T,D].
// ---------------------------------------------------------------------------
#define GSTR 40
#define TILE_B (128 * GSTR * 2)

template <int MODE>
__global__ __launch_bounds__(256)
void gemm_f16(const __half* __restrict__ A, const __half* __restrict__ W,
              __half* __restrict__ out, int N)
{
    __shared__ __align__(16) char smem[2 * 2 * TILE_B];
    const uint32_t sb = smem_u32(smem);

    const int tid = threadIdx.x;
    const int lane = tid & 31;
    const int wid = tid >> 5;
    const int wm = wid >> 2;
    const int wn = wid & 3;
    const int m0 = blockIdx.y * 128, n0 = blockIdx.x * 128;

    const int NTOT = K_DIM / 32;      // 64

    auto load_chunk = [&](int c) {
        int k0 = c * 32;
        uint32_t st = sb + (uint32_t)(c & 1) * (2 * TILE_B);
        const __half* As = A + (size_t)m0 * K_DIM + k0;
        const __half* Bs = W + (size_t)n0 * K_DIM + k0;
#pragma unroll
        for (int i = 0; i < 4; i++) {
            int idx = tid + i * 256;
            int rem = idx & 511;
            int r = rem >> 2, c4 = rem & 3;
            const __half* src = (idx < 512)
                ? (As + (size_t)r * K_DIM + c4 * 8)
                : (Bs + (size_t)r * K_DIM + c4 * 8);
            uint32_t dst = st + (uint32_t)((idx < 512) ? 0 : TILE_B)
                         + (uint32_t)(r * (GSTR * 2) + c4 * 16);
            cp_async16(dst, src);
        }
        cp_commit();
    };

    float acc[4][4][4];
#pragma unroll
    for (int mi = 0; mi < 4; mi++)
#pragma unroll
        for (int nf = 0; nf < 4; nf++)
#pragma unroll
            for (int e = 0; e < 4; e++) acc[mi][nf][e] = 0.f;

    const int a_row = lane & 15;
    const int a_col8 = (lane >> 4) * 8;
    const int b_row = (lane & 7) + ((lane & 16) >> 1);
    const int b_col8 = (lane & 8);

    load_chunk(0);

    for (int c = 0; c < NTOT; c++) {
        if (c + 1 < NTOT) { load_chunk(c + 1); cp_wait1(); }
        else              { cp_wait0(); }
        __syncthreads();

        uint32_t st = sb + (uint32_t)(c & 1) * (2 * TILE_B);
        uint32_t aBase = st;
        uint32_t bBase = st + TILE_B;

#pragma unroll
        for (int s = 0; s < 2; s++) {
            uint32_t a[4][4];
#pragma unroll
            for (int mi = 0; mi < 4; mi++) {
                uint32_t addr = aBase + (uint32_t)(
                    (wm * 64 + mi * 16 + a_row) * (GSTR * 2) + (s * 16 + a_col8) * 2);
                ldsm4(a[mi][0], a[mi][1], a[mi][2], a[mi][3], addr);
            }
            uint32_t b[2][4];
#pragma unroll
            for (int nj = 0; nj < 2; nj++) {
                uint32_t addr = bBase + (uint32_t)(
                    (wn * 32 + nj * 16 + b_row) * (GSTR * 2) + (s * 16 + b_col8) * 2);
                ldsm4(b[nj][0], b[nj][1], b[nj][2], b[nj][3], addr);
            }
#pragma unroll
            for (int mi = 0; mi < 4; mi++)
#pragma unroll
                for (int nf = 0; nf < 4; nf++)
                    mma_f16(acc[mi][nf], a[mi],
                            b[nf >> 1][(nf & 1) * 2], b[nf >> 1][(nf & 1) * 2 + 1]);
        }
        __syncthreads();
    }

    // epilogue: (e,o) adjacent col pair per acc half
#pragma unroll
    for (int mi = 0; mi < 4; mi++) {
        int r_loc = wm * 64 + mi * 16 + (lane >> 2);
#pragma unroll
        for (int half = 0; half < 2; half++) {
            int mr = m0 + r_loc + half * 8;
            int bb = mr >> 11;
            int t  = mr & (T_DIM - 1);
#pragma unroll
            for (int nf = 0; nf < 4; nf++) {
                int n = n0 + wn * 32 + nf * 8 + (lane & 3) * 2;
                float e = acc[mi][nf][half * 2];
                float o = acc[mi][nf][half * 2 + 1];
                int hh = n >> 7, d = n & (HD - 1);
                if (MODE == 2) {
                    *(__half2*)&out[(((size_t)bb * N_KV + hh) * T_DIM + t) * HD + d]
                        = __floats2half2_rn(e, o);
                } else {
                    float cs = g_cos[t * 64 + (d >> 1)];
                    float sn = g_sin[t * 64 + (d >> 1)];
                    float oe = e * cs - o * sn;
                    float oo = e * sn + o * cs;
                    size_t idx;
                    if (MODE == 0) {
                        oe *= QK_SCALE; oo *= QK_SCALE;
                        idx = (((size_t)bb * N_HEAD + hh) * T_DIM + t) * HD + d;
                    } else {
                        idx = (((size_t)bb * N_KV + hh) * T_DIM + t) * HD + d;
                    }
                    *(__half2*)&out[idx] = __floats2half2_rn(oe, oo);
                }
            }
        }
    }
}

// ---------------------------------------------------------------------------
// bf16x3 NT GEMM for O-projection (MODE 3 of round-4 kernel, verified)
// ---------------------------------------------------------------------------
__global__ __launch_bounds__(256)
void gemm_bf16x3(const __nv_bfloat16* __restrict__ Ahi, const __nv_bfloat16* __restrict__ Alo,
                 const __nv_bfloat16* __restrict__ Bhi, const __nv_bfloat16* __restrict__ Blo,
                 float* __restrict__ out, int N)
{
    __shared__ __align__(16) char smem[2 * 2 * TILE_B];
    const uint32_t sb = smem_u32(smem);

    const int tid = threadIdx.x;
    const int lane = tid & 31;
    const int wid = tid >> 5;
    const int wm = wid >> 2;
    const int wn = wid & 3;
    const int m0 = blockIdx.y * 128, n0 = blockIdx.x * 128;

    const __nv_bfloat16* Ap[3] = { Ahi, Ahi, Alo };
    const __nv_bfloat16* Bp[3] = { Bhi, Blo, Bhi };

    const int NCH = K_DIM / 32;
    const int NTOT = 3 * NCH;

    auto load_chunk = [&](int c) {
        int pass = c / NCH;
        int k0 = (c - pass * NCH) * 32;
        uint32_t st = sb + (uint32_t)(c & 1) * (2 * TILE_B);
        const __nv_bfloat16* As = Ap[pass] + (size_t)m0 * K_DIM + k0;
        const __nv_bfloat16* Bs = Bp[pass] + (size_t)n0 * K_DIM + k0;
#pragma unroll
        for (int i = 0; i < 4; i++) {
            int idx = tid + i * 256;
            int rem = idx & 511;
            int r = rem >> 2, c4 = rem & 3;
            const __nv_bfloat16* src = (idx < 512)
                ? (As + (size_t)r * K_DIM + c4 * 8)
                : (Bs + (size_t)r * K_DIM + c4 * 8);
            uint32_t dst = st + (uint32_t)((idx < 512) ? 0 : TILE_B)
                         + (uint32_t)(r * (GSTR * 2) + c4 * 16);
            cp_async16(dst, src);
        }
        cp_commit();
    };

    float acc[4][4][4];
#pragma unroll
    for (int mi = 0; mi < 4; mi++)
#pragma unroll
        for (int nf = 0; nf < 4; nf++)
#pragma unroll
            for (int e = 0; e < 4; e++) acc[mi][nf][e] = 0.f;

    const int a_row = lane & 15;
    const int a_col8 = (lane >> 4) * 8;
    const int b_row = (lane & 7) + ((lane & 16) >> 1);
    const int b_col8 = (lane & 8);

    load_chunk(0);

    for (int c = 0; c < NTOT; c++) {
        if (c + 1 < NTOT) { load_chunk(c + 1); cp_wait1(); }
        else              { cp_wait0(); }
        __syncthreads();

        uint32_t st = sb + (uint32_t)(c & 1) * (2 * TILE_B);
        uint32_t aBase = st;
        uint32_t bBase = st + TILE_B;

#pragma unroll
        for (int s = 0; s < 2; s++) {
            uint32_t a[4][4];
#pragma unroll
            for (int mi = 0; mi < 4; mi++) {
                uint32_t addr = aBase + (uint32_t)(
                    (wm * 64 + mi * 16 + a_row) * (GSTR * 2) + (s * 16 + a_col8) * 2);
                ldsm4(a[mi][0], a[mi][1], a[mi][2], a[mi][3], addr);
            }
            uint32_t b[2][4];
#pragma unroll
            for (int nj = 0; nj < 2; nj++) {
                uint32_t addr = bBase + (uint32_t)(
                    (wn * 32 + nj * 16 + b_row) * (GSTR * 2) + (s * 16 + b_col8) * 2);
                ldsm4(b[nj][0], b[nj][1], b[nj][2], b[nj][3], addr);
            }
#pragma unroll
            for (int mi = 0; mi < 4; mi++)
#pragma unroll
                for (int nf = 0; nf < 4; nf++)
                    mma_bf16(acc[mi][nf], a[mi],
                             b[nf >> 1][(nf & 1) * 2], b[nf >> 1][(nf & 1) * 2 + 1]);
        }
        __syncthreads();
    }

#pragma unroll
    for (int mi = 0; mi < 4; mi++) {
        int r_loc = wm * 64 + mi * 16 + (lane >> 2);
#pragma unroll
        for (int half = 0; half < 2; half++) {
            int mr = m0 + r_loc + half * 8;
#pragma unroll
            for (int nf = 0; nf < 4; nf++) {
                int n = n0 + wn * 32 + nf * 8 + (lane & 3) * 2;
                *(float2*)&out[(size_t)mr * N + n] =
                    make_float2(acc[mi][nf][half * 2], acc[mi][nf][half * 2 + 1]);
            }
        }
    }
}

// ---------------------------------------------------------------------------
// fp16 tensor-core flash attention (FA2).
// BQ=128, BK=64, 256 threads = 8 warps; warp owns 16 q-rows x full tile.
// S: Q(frag-resident) @ K^T via mma; P repacked in-registers to A-frags;
// PV via ldmatrix.trans on V. Output: bf16 hi/lo pair for O-projection.
// Smem row stride 272B (128 halves + 8 pad) -> conflict-free ldsm.
// ---------------------------------------------------------------------------
#define FSTR 136                      // halves per row
#define FQ_B (128 * FSTR * 2)         // 34816
#define FKV_B (64 * FSTR * 2)         // 17408
#define FL_SMEM (FQ_B + 2 * 2 * FKV_B)  // 104448

__global__ __launch_bounds__(256, 1)
void flash_tc(const int* __restrict__ amask,
              __nv_bfloat16* __restrict__ ohi, __nv_bfloat16* __restrict__ olo)
{
    extern __shared__ __align__(16) char smem[];
    const uint32_t sb = smem_u32(smem);
    __shared__ uint32_t s_ms[2][2];

    const int tid = threadIdx.x;
    const int lane = tid & 31;
    const int wid = tid >> 5;
    const int qt = blockIdx.x;
    const int h  = blockIdx.y;
    const int b  = blockIdx.z;
    const int kvh = h & (N_KV - 1);

    const __half* qb = g_qh + (((size_t)b * N_HEAD + h) * T_DIM + qt * 128) * HD;
    const __half* kb = g_kh + (((size_t)b * N_KV + kvh) * T_DIM) * HD;
    const __half* vb = g_vh + (((size_t)b * N_KV + kvh) * T_DIM) * HD;

    // ---- stage Q tile ----
#pragma unroll
    for (int i = 0; i < 8; i++) {
        int idx = tid + i * 256;          // 0..2047
        int r = idx >> 4, c16 = idx & 15;
        cp_async16(sb + (uint32_t)(r * (FSTR * 2) + c16 * 16),
                   qb + (size_t)r * HD + c16 * 8);
    }
    cp_commit();

    auto load_tile = [&](int c) {
        uint32_t st = sb + FQ_B + (uint32_t)(c & 1) * (2 * FKV_B);
        const __half* ks = kb + (size_t)c * 64 * HD;
        const __half* vs = vb + (size_t)c * 64 * HD;
#pragma unroll
        for (int i = 0; i < 8; i++) {
            int idx = tid + i * 256;      // 0..2047
            int rem = idx & 1023;
            int r = rem >> 4, c16 = rem & 15;
            const __half* src = (idx < 1024) ? (ks + (size_t)r * HD + c16 * 8)
                                             : (vs + (size_t)r * HD + c16 * 8);
            uint32_t dst = st + (uint32_t)((idx < 1024) ? 0 : FKV_B)
                         + (uint32_t)(r * (FSTR * 2) + c16 * 16);
            cp_async16(dst, src);
        }
        cp_commit();
        if (tid < 64) {
            int v = amask[b * T_DIM + c * 64 + tid];
            uint32_t bal = __ballot_sync(0xffffffffu, v != 0);
            if ((tid & 31) == 0) s_ms[c & 1][tid >> 5] = bal;
        }
    };

    load_tile(0);
    cp_wait0();
    __syncthreads();

    // ---- Q fragments (resident) ----
    uint32_t qa[8][4];
    {
        const int a_row = lane & 15;
        const int a_col8 = (lane >> 4) * 8;
#pragma unroll
        for (int s = 0; s < 8; s++) {
            uint32_t addr = sb + (uint32_t)(
                (wid * 16 + a_row) * (FSTR * 2) + (s * 16 + a_col8) * 2);
            ldsm4(qa[s][0], qa[s][1], qa[s][2], qa[s][3], addr);
        }
    }

    float o[16][4];
#pragma unroll
    for (int nf = 0; nf < 16; nf++)
#pragma unroll
        for (int e = 0; e < 4; e++) o[nf][e] = 0.f;
    float m_i[2] = {-1e30f, -1e30f};
    float l_i[2] = {0.f, 0.f};

    const int b_row = (lane & 7) + ((lane & 16) >> 1);
    const int b_col8 = (lane & 8);
    const int row_in_warp = lane >> 2;
    const int qg_base = qt * 128 + wid * 16 + row_in_warp;   // rows: +0 and +8

    const int nkt = 2 * qt + 2;
    for (int kt = 0; kt < nkt; kt++) {
        if (kt + 1 < nkt) { load_tile(kt + 1); cp_wait1(); }
        else              { cp_wait0(); }
        __syncthreads();

        uint32_t kBase = sb + FQ_B + (uint32_t)(kt & 1) * (2 * FKV_B);
        uint32_t vBase = kBase + FKV_B;

        // ---- S = Q @ K^T : warp computes 16 x 64 ----
        float s[8][4];
#pragma unroll
        for (int nb = 0; nb < 8; nb++)
#pragma unroll
            for (int e = 0; e < 4; e++) s[nb][e] = 0.f;

#pragma unroll
        for (int ks = 0; ks < 8; ks++) {
            uint32_t bb[4][4];
#pragma unroll
            for (int nb2 = 0; nb2 < 4; nb2++) {
                uint32_t addr = kBase + (uint32_t)(
                    (nb2 * 16 + b_row) * (FSTR * 2) + (ks * 16 + b_col8) * 2);
                ldsm4(bb[nb2][0], bb[nb2][1], bb[nb2][2], bb[nb2][3], addr);
            }
#pragma unroll
            for (int nb2 = 0; nb2 < 4; nb2++) {
                mma_f16(s[2 * nb2],     qa[ks], bb[nb2][0], bb[nb2][1]);
                mma_f16(s[2 * nb2 + 1], qa[ks], bb[nb2][2], bb[nb2][3]);
            }
        }

        // ---- mask ----
        const uint32_t w0 = s_ms[kt & 1][0], w1 = s_ms[kt & 1][1];
        const bool diag = (kt >= 2 * qt);
        const bool full_pad = (w0 == 0xffffffffu) && (w1 == 0xffffffffu);
        if (diag || !full_pad) {
#pragma unroll
            for (int nb = 0; nb < 8; nb++)
#pragma unroll
                for (int e = 0; e < 4; e++) {
                    int col = nb * 8 + (lane & 3) * 2 + (e & 1);
                    bool ok = ((col < 32 ? (w0 >> col) : (w1 >> (col - 32))) & 1u) != 0u;
                    if (diag)
                        ok = ok && (kt * 64 + col <= qg_base + (e >> 1) * 8);
                    if (!ok) s[nb][e] = -1e30f;
                }
        }

        // ---- online softmax (rows r and r+8 per thread) ----
        float mx[2] = {-1e30f, -1e30f};
#pragma unroll
        for (int nb = 0; nb < 8; nb++)
#pragma unroll
            for (int e = 0; e < 4; e++) mx[e >> 1] = fmaxf(mx[e >> 1], s[nb][e]);
#pragma unroll
        for (int i = 0; i < 2; i++) {
            mx[i] = fmaxf(mx[i], __shfl_xor_sync(0xffffffffu, mx[i], 1));
            mx[i] = fmaxf(mx[i], __shfl_xor_sync(0xffffffffu, mx[i], 2));
        }
        float alpha[2], rs[2] = {0.f, 0.f};
#pragma unroll
        for (int i = 0; i < 2; i++) {
            float mn = fmaxf(m_i[i], mx[i]);
            alpha[i] = exp2p((m_i[i] - mn) * LOG2E);
            m_i[i] = mn;
        }
#pragma unroll
        for (int nb = 0; nb < 8; nb++)
#pragma unroll
            for (int e = 0; e < 4; e++) {
                float p = exp2p((s[nb][e] - m_i[e >> 1]) * LOG2E);
                s[nb][e] = p;
                rs[e >> 1] += p;
            }
#pragma unroll
        for (int i = 0; i < 2; i++) {
            rs[i] += __shfl_xor_sync(0xffffffffu, rs[i], 1);
            rs[i] += __shfl_xor_sync(0xffffffffu, rs[i], 2);
            l_i[i] = l_i[i] * alpha[i] + rs[i];
        }

        // ---- O *= alpha ----
#pragma unroll
        for (int nf = 0; nf < 16; nf++) {
            o[nf][0] *= alpha[0]; o[nf][1] *= alpha[0];
            o[nf][2] *= alpha[1]; o[nf][3] *= alpha[1];
        }

        // ---- O += P @ V ----
#pragma unroll
        for (int kb = 0; kb < 4; kb++) {
            uint32_t pa[4];
            pa[0] = pack_h2(s[2 * kb][0], s[2 * kb][1]);
            pa[1] = pack_h2(s[2 * kb][2], s[2 * kb][3]);
            pa[2] = pack_h2(s[2 * kb + 1][0], s[2 * kb + 1][1]);
            pa[3] = pack_h2(s[2 * kb + 1][2], s[2 * kb + 1][3]);
#pragma unroll
            for (int nd2 = 0; nd2 < 8; nd2++) {
                uint32_t v0, v1, v2, v3;
                uint32_t addr = vBase + (uint32_t)(
                    (kb * 16 + (lane & 15)) * (FSTR * 2)
                    + (nd2 * 16 + (lane >> 4) * 8) * 2);
                ldsm4t(v0, v1, v2, v3, addr);
                mma_f16(o[2 * nd2],     pa, v0, v1);
                mma_f16(o[2 * nd2 + 1], pa, v2, v3);
            }
        }
        __syncthreads();   // protect K/V buffer before next load overwrites
    }

    // ---- epilogue: write bf16 hi/lo for O-projection ----
    float inv[2] = {1.f / l_i[0], 1.f / l_i[1]};
#pragma unroll
    for (int half = 0; half < 2; half++) {
        size_t row = (size_t)b * T_DIM + qt * 128 + wid * 16 + row_in_warp + half * 8;
#pragma unroll
        for (int nf = 0; nf < 16; nf++) {
            int cc = h * HD + nf * 8 + (lane & 3) * 2;
            float e = o[nf][half * 2] * inv[half];
            float od = o[nf][half * 2 + 1] * inv[half];
            __nv_bfloat16 he = __float2bfloat16(e);
            __nv_bfloat16 ho = __float2bfloat16(od);
            __nv_bfloat162 hh(he, ho);
            __nv_bfloat162 ll(__float2bfloat16(e - __bfloat162float(he)),
                              __float2bfloat16(od - __bfloat162float(ho)));
            *(__nv_bfloat162*)&ohi[row * C_DIM + cc] = hh;
            *(__nv_bfloat162*)&olo[row * C_DIM + cc] = ll;
        }
    }
}

// ---------------------------------------------------------------------------
// Launch
// ---------------------------------------------------------------------------
extern "C" void kernel_launch(void* const* d_in, const int* in_sizes, int n_in,
                              void* d_out, int out_size)
{
    const float* x    = (const float*)d_in[0];
    const float* rope = (const float*)d_in[1];
    const int*   am   = (const int*)  d_in[2];
    const float* Wq   = (const float*)d_in[3];
    const float* Wk   = (const float*)d_in[4];
    const float* Wv   = (const float*)d_in[5];
    const float* Wo   = (const float*)d_in[6];
    float* out = (float*)d_out;

    __half *xh, *wq16, *wk16, *wv16, *qh, *kh, *vh;
    __nv_bfloat16 *ahi, *alo, *woh, *wol;
    cudaGetSymbolAddress((void**)&xh, g_xh);
    cudaGetSymbolAddress((void**)&wq16, g_wq16);
    cudaGetSymbolAddress((void**)&wk16, g_wk16);
    cudaGetSymbolAddress((void**)&wv16, g_wv16);
    cudaGetSymbolAddress((void**)&qh, g_qh);
    cudaGetSymbolAddress((void**)&kh, g_kh);
    cudaGetSymbolAddress((void**)&vh, g_vh);
    cudaGetSymbolAddress((void**)&ahi, g_ahi);
    cudaGetSymbolAddress((void**)&alo, g_alo);
    cudaGetSymbolAddress((void**)&woh, g_woh);
    cudaGetSymbolAddress((void**)&wol, g_wol);

    cudaFuncSetAttribute(flash_tc, cudaFuncAttributeMaxDynamicSharedMemorySize, FL_SMEM);

    // launches 0..4 (so ncu -s 5 profiles gemm_f16<0>)
    rope_tables_kernel<<<(T_DIM * 64 + 255) / 256, 256>>>(rope);
    to_f16<<<(M_TOT * K_DIM / 8 + 255) / 256, 256>>>(x, xh, M_TOT * K_DIM / 8);
    to_f16<<<(C_DIM * K_DIM / 8 + 255) / 256, 256>>>(Wq, wq16, C_DIM * K_DIM / 8);
    to_f16<<<(NKV_C * K_DIM / 8 + 255) / 256, 256>>>(Wk, wk16, NKV_C * K_DIM / 8);
    to_f16<<<(NKV_C * K_DIM / 8 + 255) / 256, 256>>>(Wv, wv16, NKV_C * K_DIM / 8);

    // projections (fp16 mma)
    gemm_f16<0><<<dim3(C_DIM / 128, M_TOT / 128), 256>>>(xh, wq16, qh, C_DIM);
    gemm_f16<1><<<dim3(NKV_C / 128, M_TOT / 128), 256>>>(xh, wk16, kh, NKV_C);
    gemm_f16<2><<<dim3(NKV_C / 128, M_TOT / 128), 256>>>(xh, wv16, vh, NKV_C);

    // attention (fp16 tensor cores), writes bf16 hi/lo
    flash_tc<<<dim3(T_DIM / 128, N_HEAD, B_DIM), 256, FL_SMEM>>>(am, ahi, alo);

    // O projection (bf16x3, fp32-accurate)
    to_bf16_pair<<<(C_DIM * K_DIM / 8 + 255) / 256, 256>>>(Wo, woh, wol, C_DIM * K_DIM / 8);
    gemm_bf16x3<<<dim3(C_DIM / 128, M_TOT / 128), 256>>>(ahi, alo, woh, wol, out, C_DIM);
}

// round 8
// speedup vs baseline: 8.2280x; 1.4739x over previous
#include <cuda_runtime.h>
#include <cuda_bf16.h>
#include <cuda_fp16.h>
#include <math.h>
#include <cstdint>

// ---------------------------------------------------------------------------
#define B_DIM 4
#define T_DIM 2048
#define C_DIM 2048
#define N_HEAD 16
#define N_KV 4
#define HD 128
#define M_TOT (B_DIM * T_DIM)           // 8192
#define K_DIM 2048
#define NKV_C (N_KV * HD)               // 512
#define QK_SCALE 0.08838834764831845f   // 1/sqrt(128)
#define LOG2E 1.4426950408889634f

// ---------------------------------------------------------------------------
// Scratch (static device globals)
// ---------------------------------------------------------------------------
__device__ __half g_xh[(size_t)M_TOT * K_DIM];
__device__ __half g_wq16[(size_t)C_DIM * K_DIM];
__device__ __half g_wk16[(size_t)NKV_C * K_DIM];
__device__ __half g_wv16[(size_t)NKV_C * K_DIM];
__device__ __half g_wo16[(size_t)C_DIM * K_DIM];
__device__ __half g_qh[(size_t)B_DIM * N_HEAD * T_DIM * HD];  // [B,H,T,D]
__device__ __half g_kh[(size_t)B_DIM * N_KV * T_DIM * HD];
__device__ __half g_vh[(size_t)B_DIM * N_KV * T_DIM * HD];
__device__ __half g_ah[(size_t)M_TOT * C_DIM];                // attn out fp16
__device__ float g_cos[(size_t)T_DIM * 64];
__device__ float g_sin[(size_t)T_DIM * 64];

// ---------------------------------------------------------------------------
// Helpers (sm_100-safe)
// ---------------------------------------------------------------------------
__device__ __forceinline__ uint32_t smem_u32(const void* p) {
    uint32_t a;
    asm("{ .reg .u64 t; cvta.to.shared.u64 t, %1; cvt.u32.u64 %0, t; }"
        : "=r"(a) : "l"(p));
    return a;
}
__device__ __forceinline__ void cp_async16(uint32_t dst, const void* src) {
    asm volatile("cp.async.cg.shared.global [%0], [%1], 16;" :: "r"(dst), "l"(src));
}
__device__ __forceinline__ void cp_commit() {
    asm volatile("cp.async.commit_group;" ::: "memory");
}
__device__ __forceinline__ void cp_wait1() {
    asm volatile("cp.async.wait_group 1;" ::: "memory");
}
__device__ __forceinline__ void cp_wait0() {
    asm volatile("cp.async.wait_group 0;" ::: "memory");
}
__device__ __forceinline__ void ldsm4(uint32_t& r0, uint32_t& r1, uint32_t& r2,
                                      uint32_t& r3, uint32_t addr) {
    asm volatile("ldmatrix.sync.aligned.m8n8.x4.shared.b16 {%0,%1,%2,%3}, [%4];"
                 : "=r"(r0), "=r"(r1), "=r"(r2), "=r"(r3) : "r"(addr));
}
__device__ __forceinline__ void ldsm4t(uint32_t& r0, uint32_t& r1, uint32_t& r2,
                                       uint32_t& r3, uint32_t addr) {
    asm volatile("ldmatrix.sync.aligned.m8n8.x4.trans.shared.b16 {%0,%1,%2,%3}, [%4];"
                 : "=r"(r0), "=r"(r1), "=r"(r2), "=r"(r3) : "r"(addr));
}
__device__ __forceinline__ void mma_f16(float* d, const uint32_t* a,
                                        uint32_t b0, uint32_t b1) {
    asm volatile(
        "mma.sync.aligned.m16n8k16.row.col.f32.f16.f16.f32 "
        "{%0,%1,%2,%3}, {%4,%5,%6,%7}, {%8,%9}, {%0,%1,%2,%3};"
        : "+f"(d[0]), "+f"(d[1]), "+f"(d[2]), "+f"(d[3])
        : "r"(a[0]), "r"(a[1]), "r"(a[2]), "r"(a[3]), "r"(b0), "r"(b1));
}
// fast exp2: degree-5 poly, FFMA pipe only (no MUFU)
__device__ __forceinline__ float exp2p(float x) {
    x = fmaxf(x, -126.f);
    float t = rintf(x);
    float f = x - t;
    float p = 0.0013333558f;
    p = fmaf(p, f, 0.0096181291f);
    p = fmaf(p, f, 0.0555041087f);
    p = fmaf(p, f, 0.2402265070f);
    p = fmaf(p, f, 0.6931471806f);
    p = fmaf(p, f, 1.0f);
    return __int_as_float(__float_as_int(p) + (((int)t) << 23));
}
__device__ __forceinline__ uint32_t pack_h2(float x, float y) {
    __half2 h = __floats2half2_rn(x, y);
    return *(uint32_t*)&h;
}

// ---------------------------------------------------------------------------
// Prep kernels
// ---------------------------------------------------------------------------
__global__ void rope_tables_kernel(const float* __restrict__ rope) {
    int i = blockIdx.x * 256 + threadIdx.x;
    if (i < T_DIM * 64) {
        float sn, cs;
        sincosf(rope[i], &sn, &cs);
        g_sin[i] = sn; g_cos[i] = cs;
    }
}

__global__ void to_f16(const float* __restrict__ src, __half* __restrict__ dst, int n8) {
    int i = blockIdx.x * 256 + threadIdx.x;
    if (i >= n8) return;
    const float4* s4 = (const float4*)src;
    float4 a = s4[2 * i], b = s4[2 * i + 1];
    __half2 h0 = __floats2half2_rn(a.x, a.y);
    __half2 h1 = __floats2half2_rn(a.z, a.w);
    __half2 h2 = __floats2half2_rn(b.x, b.y);
    __half2 h3 = __floats2half2_rn(b.z, b.w);
    uint4 u;
    u.x = *(uint32_t*)&h0; u.y = *(uint32_t*)&h1;
    u.z = *(uint32_t*)&h2; u.w = *(uint32_t*)&h3;
    ((uint4*)dst)[i] = u;
}

// ---------------------------------------------------------------------------
// fp16 single-pass NT GEMM: out = A[M,K] @ W[N,K]^T, fp32 accum.
// 128x128 tile/CTA, BK=32, 256 threads, warp tile 64x32.
// MODE 0: Q proj -> RoPE+scale, [B,H,T,D] (half); 1: K proj -> RoPE (half);
// MODE 2: V proj (half); 3: O proj -> row-major float [M,N].
// ---------------------------------------------------------------------------
#define GSTR 40
#define TILE_B (128 * GSTR * 2)

template <int MODE>
__global__ __launch_bounds__(256)
void gemm_f16(const __half* __restrict__ A, const __half* __restrict__ W,
              __half* __restrict__ out, float* __restrict__ outf, int N)
{
    __shared__ __align__(16) char smem[2 * 2 * TILE_B];
    const uint32_t sb = smem_u32(smem);

    const int tid = threadIdx.x;
    const int lane = tid & 31;
    const int wid = tid >> 5;
    const int wm = wid >> 2;
    const int wn = wid & 3;
    const int m0 = blockIdx.y * 128, n0 = blockIdx.x * 128;

    const int NTOT = K_DIM / 32;      // 64

    auto load_chunk = [&](int c) {
        int k0 = c * 32;
        uint32_t st = sb + (uint32_t)(c & 1) * (2 * TILE_B);
        const __half* As = A + (size_t)m0 * K_DIM + k0;
        const __half* Bs = W + (size_t)n0 * K_DIM + k0;
#pragma unroll
        for (int i = 0; i < 4; i++) {
            int idx = tid + i * 256;
            int rem = idx & 511;
            int r = rem >> 2, c4 = rem & 3;
            const __half* src = (idx < 512)
                ? (As + (size_t)r * K_DIM + c4 * 8)
                : (Bs + (size_t)r * K_DIM + c4 * 8);
            uint32_t dst = st + (uint32_t)((idx < 512) ? 0 : TILE_B)
                         + (uint32_t)(r * (GSTR * 2) + c4 * 16);
            cp_async16(dst, src);
        }
        cp_commit();
    };

    float acc[4][4][4];
#pragma unroll
    for (int mi = 0; mi < 4; mi++)
#pragma unroll
        for (int nf = 0; nf < 4; nf++)
#pragma unroll
            for (int e = 0; e < 4; e++) acc[mi][nf][e] = 0.f;

    const int a_row = lane & 15;
    const int a_col8 = (lane >> 4) * 8;
    const int b_row = (lane & 7) + ((lane & 16) >> 1);
    const int b_col8 = (lane & 8);

    load_chunk(0);

    for (int c = 0; c < NTOT; c++) {
        if (c + 1 < NTOT) { load_chunk(c + 1); cp_wait1(); }
        else              { cp_wait0(); }
        __syncthreads();

        uint32_t st = sb + (uint32_t)(c & 1) * (2 * TILE_B);
        uint32_t aBase = st;
        uint32_t bBase = st + TILE_B;

#pragma unroll
        for (int s = 0; s < 2; s++) {
            uint32_t a[4][4];
#pragma unroll
            for (int mi = 0; mi < 4; mi++) {
                uint32_t addr = aBase + (uint32_t)(
                    (wm * 64 + mi * 16 + a_row) * (GSTR * 2) + (s * 16 + a_col8) * 2);
                ldsm4(a[mi][0], a[mi][1], a[mi][2], a[mi][3], addr);
            }
            uint32_t b[2][4];
#pragma unroll
            for (int nj = 0; nj < 2; nj++) {
                uint32_t addr = bBase + (uint32_t)(
                    (wn * 32 + nj * 16 + b_row) * (GSTR * 2) + (s * 16 + b_col8) * 2);
                ldsm4(b[nj][0], b[nj][1], b[nj][2], b[nj][3], addr);
            }
#pragma unroll
            for (int mi = 0; mi < 4; mi++)
#pragma unroll
                for (int nf = 0; nf < 4; nf++)
                    mma_f16(acc[mi][nf], a[mi],
                            b[nf >> 1][(nf & 1) * 2], b[nf >> 1][(nf & 1) * 2 + 1]);
        }
        __syncthreads();
    }

    // epilogue: (e,o) adjacent col pair per acc half
#pragma unroll
    for (int mi = 0; mi < 4; mi++) {
        int r_loc = wm * 64 + mi * 16 + (lane >> 2);
#pragma unroll
        for (int half = 0; half < 2; half++) {
            int mr = m0 + r_loc + half * 8;
            int bb = mr >> 11;
            int t  = mr & (T_DIM - 1);
#pragma unroll
            for (int nf = 0; nf < 4; nf++) {
                int n = n0 + wn * 32 + nf * 8 + (lane & 3) * 2;
                float e = acc[mi][nf][half * 2];
                float o = acc[mi][nf][half * 2 + 1];
                if (MODE == 3) {
                    *(float2*)&outf[(size_t)mr * N + n] = make_float2(e, o);
                } else {
                    int hh = n >> 7, d = n & (HD - 1);
                    if (MODE == 2) {
                        *(__half2*)&out[(((size_t)bb * N_KV + hh) * T_DIM + t) * HD + d]
                            = __floats2half2_rn(e, o);
                    } else {
                        float cs = g_cos[t * 64 + (d >> 1)];
                        float sn = g_sin[t * 64 + (d >> 1)];
                        float oe = e * cs - o * sn;
                        float oo = e * sn + o * cs;
                        size_t idx;
                        if (MODE == 0) {
                            oe *= QK_SCALE; oo *= QK_SCALE;
                            idx = (((size_t)bb * N_HEAD + hh) * T_DIM + t) * HD + d;
                        } else {
                            idx = (((size_t)bb * N_KV + hh) * T_DIM + t) * HD + d;
                        }
                        *(__half2*)&out[idx] = __floats2half2_rn(oe, oo);
                    }
                }
            }
        }
    }
}

// ---------------------------------------------------------------------------
// fp16 tensor-core flash attention (FA2).
// BQ=128, BK=64, 256 threads = 8 warps; warp owns 16 q-rows x full tile.
// S: Q(frag-resident) @ K^T via mma; P repacked in-registers to A-frags;
// PV via ldmatrix.trans on V. Output: fp16 row-major [B*T, C] for O-proj.
// Smem row stride 272B (128 halves + 8 pad) -> conflict-free ldsm.
// ---------------------------------------------------------------------------
#define FSTR 136                      // halves per row
#define FQ_B (128 * FSTR * 2)         // 34816
#define FKV_B (64 * FSTR * 2)         // 17408
#define FL_SMEM (FQ_B + 2 * 2 * FKV_B)  // 104448

__global__ __launch_bounds__(256, 1)
void flash_tc(const int* __restrict__ amask, __half* __restrict__ oh)
{
    extern __shared__ __align__(16) char smem[];
    const uint32_t sb = smem_u32(smem);
    __shared__ uint32_t s_ms[2][2];

    const int tid = threadIdx.x;
    const int lane = tid & 31;
    const int wid = tid >> 5;
    const int qt = blockIdx.x;
    const int h  = blockIdx.y;
    const int b  = blockIdx.z;
    const int kvh = h & (N_KV - 1);

    const __half* qb = g_qh + (((size_t)b * N_HEAD + h) * T_DIM + qt * 128) * HD;
    const __half* kb = g_kh + (((size_t)b * N_KV + kvh) * T_DIM) * HD;
    const __half* vb = g_vh + (((size_t)b * N_KV + kvh) * T_DIM) * HD;

    // ---- stage Q tile ----
#pragma unroll
    for (int i = 0; i < 8; i++) {
        int idx = tid + i * 256;          // 0..2047
        int r = idx >> 4, c16 = idx & 15;
        cp_async16(sb + (uint32_t)(r * (FSTR * 2) + c16 * 16),
                   qb + (size_t)r * HD + c16 * 8);
    }
    cp_commit();

    auto load_tile = [&](int c) {
        uint32_t st = sb + FQ_B + (uint32_t)(c & 1) * (2 * FKV_B);
        const __half* ks = kb + (size_t)c * 64 * HD;
        const __half* vs = vb + (size_t)c * 64 * HD;
#pragma unroll
        for (int i = 0; i < 8; i++) {
            int idx = tid + i * 256;      // 0..2047
            int rem = idx & 1023;
            int r = rem >> 4, c16 = rem & 15;
            const __half* src = (idx < 1024) ? (ks + (size_t)r * HD + c16 * 8)
                                             : (vs + (size_t)r * HD + c16 * 8);
            uint32_t dst = st + (uint32_t)((idx < 1024) ? 0 : FKV_B)
                         + (uint32_t)(r * (FSTR * 2) + c16 * 16);
            cp_async16(dst, src);
        }
        cp_commit();
        if (tid < 64) {
            int v = amask[b * T_DIM + c * 64 + tid];
            uint32_t bal = __ballot_sync(0xffffffffu, v != 0);
            if ((tid & 31) == 0) s_ms[c & 1][tid >> 5] = bal;
        }
    };

    load_tile(0);
    cp_wait0();
    __syncthreads();

    // ---- Q fragments (resident) ----
    uint32_t qa[8][4];
    {
        const int a_row = lane & 15;
        const int a_col8 = (lane >> 4) * 8;
#pragma unroll
        for (int s = 0; s < 8; s++) {
            uint32_t addr = sb + (uint32_t)(
                (wid * 16 + a_row) * (FSTR * 2) + (s * 16 + a_col8) * 2);
            ldsm4(qa[s][0], qa[s][1], qa[s][2], qa[s][3], addr);
        }
    }

    float o[16][4];
#pragma unroll
    for (int nf = 0; nf < 16; nf++)
#pragma unroll
        for (int e = 0; e < 4; e++) o[nf][e] = 0.f;
    float m_i[2] = {-1e30f, -1e30f};
    float l_i[2] = {0.f, 0.f};

    const int b_row = (lane & 7) + ((lane & 16) >> 1);
    const int b_col8 = (lane & 8);
    const int row_in_warp = lane >> 2;
    const int qg_base = qt * 128 + wid * 16 + row_in_warp;   // rows: +0 and +8

    const int nkt = 2 * qt + 2;
    for (int kt = 0; kt < nkt; kt++) {
        if (kt + 1 < nkt) { load_tile(kt + 1); cp_wait1(); }
        else              { cp_wait0(); }
        __syncthreads();

        uint32_t kBase = sb + FQ_B + (uint32_t)(kt & 1) * (2 * FKV_B);
        uint32_t vBase = kBase + FKV_B;

        // ---- S = Q @ K^T : warp computes 16 x 64 ----
        float s[8][4];
#pragma unroll
        for (int nb = 0; nb < 8; nb++)
#pragma unroll
            for (int e = 0; e < 4; e++) s[nb][e] = 0.f;

#pragma unroll
        for (int ks = 0; ks < 8; ks++) {
            uint32_t bb[4][4];
#pragma unroll
            for (int nb2 = 0; nb2 < 4; nb2++) {
                uint32_t addr = kBase + (uint32_t)(
                    (nb2 * 16 + b_row) * (FSTR * 2) + (ks * 16 + b_col8) * 2);
                ldsm4(bb[nb2][0], bb[nb2][1], bb[nb2][2], bb[nb2][3], addr);
            }
#pragma unroll
            for (int nb2 = 0; nb2 < 4; nb2++) {
                mma_f16(s[2 * nb2],     qa[ks], bb[nb2][0], bb[nb2][1]);
                mma_f16(s[2 * nb2 + 1], qa[ks], bb[nb2][2], bb[nb2][3]);
            }
        }

        // ---- mask ----
        const uint32_t w0 = s_ms[kt & 1][0], w1 = s_ms[kt & 1][1];
        const bool diag = (kt >= 2 * qt);
        const bool full_pad = (w0 == 0xffffffffu) && (w1 == 0xffffffffu);
        if (diag || !full_pad) {
#pragma unroll
            for (int nb = 0; nb < 8; nb++)
#pragma unroll
                for (int e = 0; e < 4; e++) {
                    int col = nb * 8 + (lane & 3) * 2 + (e & 1);
                    bool ok = ((col < 32 ? (w0 >> col) : (w1 >> (col - 32))) & 1u) != 0u;
                    if (diag)
                        ok = ok && (kt * 64 + col <= qg_base + (e >> 1) * 8);
                    if (!ok) s[nb][e] = -1e30f;
                }
        }

        // ---- online softmax (rows r and r+8 per thread) ----
        float mx[2] = {-1e30f, -1e30f};
#pragma unroll
        for (int nb = 0; nb < 8; nb++)
#pragma unroll
            for (int e = 0; e < 4; e++) mx[e >> 1] = fmaxf(mx[e >> 1], s[nb][e]);
#pragma unroll
        for (int i = 0; i < 2; i++) {
            mx[i] = fmaxf(mx[i], __shfl_xor_sync(0xffffffffu, mx[i], 1));
            mx[i] = fmaxf(mx[i], __shfl_xor_sync(0xffffffffu, mx[i], 2));
        }
        float alpha[2], rs[2] = {0.f, 0.f};
#pragma unroll
        for (int i = 0; i < 2; i++) {
            float mn = fmaxf(m_i[i], mx[i]);
            alpha[i] = exp2p((m_i[i] - mn) * LOG2E);
            m_i[i] = mn;
        }
#pragma unroll
        for (int nb = 0; nb < 8; nb++)
#pragma unroll
            for (int e = 0; e < 4; e++) {
                float p = exp2p((s[nb][e] - m_i[e >> 1]) * LOG2E);
                s[nb][e] = p;
                rs[e >> 1] += p;
            }
#pragma unroll
        for (int i = 0; i < 2; i++) {
            rs[i] += __shfl_xor_sync(0xffffffffu, rs[i], 1);
            rs[i] += __shfl_xor_sync(0xffffffffu, rs[i], 2);
            l_i[i] = l_i[i] * alpha[i] + rs[i];
        }

        // ---- O *= alpha ----
#pragma unroll
        for (int nf = 0; nf < 16; nf++) {
            o[nf][0] *= alpha[0]; o[nf][1] *= alpha[0];
            o[nf][2] *= alpha[1]; o[nf][3] *= alpha[1];
        }

        // ---- O += P @ V ----
#pragma unroll
        for (int kb = 0; kb < 4; kb++) {
            uint32_t pa[4];
            pa[0] = pack_h2(s[2 * kb][0], s[2 * kb][1]);
            pa[1] = pack_h2(s[2 * kb][2], s[2 * kb][3]);
            pa[2] = pack_h2(s[2 * kb + 1][0], s[2 * kb + 1][1]);
            pa[3] = pack_h2(s[2 * kb + 1][2], s[2 * kb + 1][3]);
#pragma unroll
            for (int nd2 = 0; nd2 < 8; nd2++) {
                uint32_t v0, v1, v2, v3;
                uint32_t addr = vBase + (uint32_t)(
                    (kb * 16 + (lane & 15)) * (FSTR * 2)
                    + (nd2 * 16 + (lane >> 4) * 8) * 2);
                ldsm4t(v0, v1, v2, v3, addr);
                mma_f16(o[2 * nd2],     pa, v0, v1);
                mma_f16(o[2 * nd2 + 1], pa, v2, v3);
            }
        }
        __syncthreads();   // protect K/V buffer before next load overwrites
    }

    // ---- epilogue: fp16 A for the O-projection ----
    float inv[2] = {1.f / l_i[0], 1.f / l_i[1]};
#pragma unroll
    for (int half = 0; half < 2; half++) {
        size_t row = (size_t)b * T_DIM + qt * 128 + wid * 16 + row_in_warp + half * 8;
#pragma unroll
        for (int nf = 0; nf < 16; nf++) {
            int cc = h * HD + nf * 8 + (lane & 3) * 2;
            *(__half2*)&oh[row * C_DIM + cc] = __floats2half2_rn(
                o[nf][half * 2] * inv[half], o[nf][half * 2 + 1] * inv[half]);
        }
    }
}

// ---------------------------------------------------------------------------
// Launch
// ---------------------------------------------------------------------------
extern "C" void kernel_launch(void* const* d_in, const int* in_sizes, int n_in,
                              void* d_out, int out_size)
{
    const float* x    = (const float*)d_in[0];
    const float* rope = (const float*)d_in[1];
    const int*   am   = (const int*)  d_in[2];
    const float* Wq   = (const float*)d_in[3];
    const float* Wk   = (const float*)d_in[4];
    const float* Wv   = (const float*)d_in[5];
    const float* Wo   = (const float*)d_in[6];
    float* out = (float*)d_out;

    __half *xh, *wq16, *wk16, *wv16, *wo16, *qh, *kh, *vh, *ah;
    cudaGetSymbolAddress((void**)&xh, g_xh);
    cudaGetSymbolAddress((void**)&wq16, g_wq16);
    cudaGetSymbolAddress((void**)&wk16, g_wk16);
    cudaGetSymbolAddress((void**)&wv16, g_wv16);
    cudaGetSymbolAddress((void**)&wo16, g_wo16);
    cudaGetSymbolAddress((void**)&qh, g_qh);
    cudaGetSymbolAddress((void**)&kh, g_kh);
    cudaGetSymbolAddress((void**)&vh, g_vh);
    cudaGetSymbolAddress((void**)&ah, g_ah);

    cudaFuncSetAttribute(flash_tc, cudaFuncAttributeMaxDynamicSharedMemorySize, FL_SMEM);

    // prep
    rope_tables_kernel<<<(T_DIM * 64 + 255) / 256, 256>>>(rope);
    to_f16<<<(M_TOT * K_DIM / 8 + 255) / 256, 256>>>(x, xh, M_TOT * K_DIM / 8);
    to_f16<<<(C_DIM * K_DIM / 8 + 255) / 256, 256>>>(Wq, wq16, C_DIM * K_DIM / 8);
    to_f16<<<(NKV_C * K_DIM / 8 + 255) / 256, 256>>>(Wk, wk16, NKV_C * K_DIM / 8);
    to_f16<<<(NKV_C * K_DIM / 8 + 255) / 256, 256>>>(Wv, wv16, NKV_C * K_DIM / 8);
    to_f16<<<(C_DIM * K_DIM / 8 + 255) / 256, 256>>>(Wo, wo16, C_DIM * K_DIM / 8);

    // projections (fp16 mma)
    gemm_f16<0><<<dim3(C_DIM / 128, M_TOT / 128), 256>>>(xh, wq16, qh, nullptr, C_DIM);
    gemm_f16<1><<<dim3(NKV_C / 128, M_TOT / 128), 256>>>(xh, wk16, kh, nullptr, NKV_C);
    gemm_f16<2><<<dim3(NKV_C / 128, M_TOT / 128), 256>>>(xh, wv16, vh, nullptr, NKV_C);

    // attention (fp16 tensor cores)
    flash_tc<<<dim3(T_DIM / 128, N_HEAD, B_DIM), 256, FL_SMEM>>>(am, ah);

    // O projection (fp16 single pass, fp32 accum)
    gemm_f16<3><<<dim3(C_DIM / 128, M_TOT / 128), 256>>>(ah, wo16, nullptr, out, C_DIM);
}

// round 11
// speedup vs baseline: 8.7578x; 1.0644x over previous
#include <cuda_runtime.h>
#include <cuda_bf16.h>
#include <cuda_fp16.h>
#include <math.h>
#include <cstdint>

// ---------------------------------------------------------------------------
#define B_DIM 4
#define T_DIM 2048
#define C_DIM 2048
#define N_HEAD 16
#define N_KV 4
#define HD 128
#define M_TOT (B_DIM * T_DIM)           // 8192
#define K_DIM 2048
#define NKV_C (N_KV * HD)               // 512
#define QK_SCALE 0.08838834764831845f   // 1/sqrt(128)
#define LOG2E 1.4426950408889634f

// ---------------------------------------------------------------------------
// Scratch (static device globals)
// ---------------------------------------------------------------------------
__device__ __half g_xh[(size_t)M_TOT * K_DIM];
__device__ __half g_wq16[(size_t)C_DIM * K_DIM];
__device__ __half g_wk16[(size_t)NKV_C * K_DIM];
__device__ __half g_wv16[(size_t)NKV_C * K_DIM];
__device__ __half g_wo16[(size_t)C_DIM * K_DIM];
__device__ __half g_qh[(size_t)B_DIM * N_HEAD * T_DIM * HD];  // [B,H,T,D]
__device__ __half g_kh[(size_t)B_DIM * N_KV * T_DIM * HD];
__device__ __half g_vh[(size_t)B_DIM * N_KV * T_DIM * HD];
__device__ __half g_ah[(size_t)M_TOT * C_DIM];                // attn out fp16
__device__ float g_cos[(size_t)T_DIM * 64];
__device__ float g_sin[(size_t)T_DIM * 64];

// ---------------------------------------------------------------------------
// Helpers (sm_100-safe)
// ---------------------------------------------------------------------------
__device__ __forceinline__ uint32_t smem_u32(const void* p) {
    uint32_t a;
    asm("{ .reg .u64 t; cvta.to.shared.u64 t, %1; cvt.u32.u64 %0, t; }"
        : "=r"(a) : "l"(p));
    return a;
}
__device__ __forceinline__ void cp_async16(uint32_t dst, const void* src) {
    asm volatile("cp.async.cg.shared.global [%0], [%1], 16;" :: "r"(dst), "l"(src));
}
__device__ __forceinline__ void cp_commit() {
    asm volatile("cp.async.commit_group;" ::: "memory");
}
__device__ __forceinline__ void cp_wait1() {
    asm volatile("cp.async.wait_group 1;" ::: "memory");
}
__device__ __forceinline__ void cp_wait0() {
    asm volatile("cp.async.wait_group 0;" ::: "memory");
}
__device__ __forceinline__ void ldsm4(uint32_t& r0, uint32_t& r1, uint32_t& r2,
                                      uint32_t& r3, uint32_t addr) {
    asm volatile("ldmatrix.sync.aligned.m8n8.x4.shared.b16 {%0,%1,%2,%3}, [%4];"
                 : "=r"(r0), "=r"(r1), "=r"(r2), "=r"(r3) : "r"(addr));
}
__device__ __forceinline__ void ldsm4t(uint32_t& r0, uint32_t& r1, uint32_t& r2,
                                       uint32_t& r3, uint32_t addr) {
    asm volatile("ldmatrix.sync.aligned.m8n8.x4.trans.shared.b16 {%0,%1,%2,%3}, [%4];"
                 : "=r"(r0), "=r"(r1), "=r"(r2), "=r"(r3) : "r"(addr));
}
__device__ __forceinline__ void mma_f16(float* d, const uint32_t* a,
                                        uint32_t b0, uint32_t b1) {
    asm volatile(
        "mma.sync.aligned.m16n8k16.row.col.f32.f16.f16.f32 "
        "{%0,%1,%2,%3}, {%4,%5,%6,%7}, {%8,%9}, {%0,%1,%2,%3};"
        : "+f"(d[0]), "+f"(d[1]), "+f"(d[2]), "+f"(d[3])
        : "r"(a[0]), "r"(a[1]), "r"(a[2]), "r"(a[3]), "r"(b0), "r"(b1));
}
// fast exp2: degree-5 poly, FFMA pipe only (no MUFU)
__device__ __forceinline__ float exp2p(float x) {
    x = fmaxf(x, -126.f);
    float t = rintf(x);
    float f = x - t;
    float p = 0.0013333558f;
    p = fmaf(p, f, 0.0096181291f);
    p = fmaf(p, f, 0.0555041087f);
    p = fmaf(p, f, 0.2402265070f);
    p = fmaf(p, f, 0.6931471806f);
    p = fmaf(p, f, 1.0f);
    return __int_as_float(__float_as_int(p) + (((int)t) << 23));
}
__device__ __forceinline__ uint32_t pack_h2(float x, float y) {
    __half2 h = __floats2half2_rn(x, y);
    return *(uint32_t*)&h;
}

// ---------------------------------------------------------------------------
// Prep kernels
// ---------------------------------------------------------------------------
__global__ void rope_tables_kernel(const float* __restrict__ rope) {
    int i = blockIdx.x * 256 + threadIdx.x;
    if (i < T_DIM * 64) {
        float sn, cs;
        sincosf(rope[i], &sn, &cs);
        g_sin[i] = sn; g_cos[i] = cs;
    }
}

__global__ void to_f16(const float* __restrict__ src, __half* __restrict__ dst, int n8) {
    int i = blockIdx.x * 256 + threadIdx.x;
    if (i >= n8) return;
    const float4* s4 = (const float4*)src;
    float4 a = s4[2 * i], b = s4[2 * i + 1];
    __half2 h0 = __floats2half2_rn(a.x, a.y);
    __half2 h1 = __floats2half2_rn(a.z, a.w);
    __half2 h2 = __floats2half2_rn(b.x, b.y);
    __half2 h3 = __floats2half2_rn(b.z, b.w);
    uint4 u;
    u.x = *(uint32_t*)&h0; u.y = *(uint32_t*)&h1;
    u.z = *(uint32_t*)&h2; u.w = *(uint32_t*)&h3;
    ((uint4*)dst)[i] = u;
}

// ---------------------------------------------------------------------------
// fp16 single-pass NT GEMM: out = A[M,K] @ W[N,K]^T, fp32 accum.
// 128x128 tile/CTA, BK=32, 256 threads, warp tile 64x32.
// 3-stage cp.async pipeline (dynamic smem, 60KB), ONE __syncthreads per chunk.
// MODE 0: Q proj -> RoPE+scale, [B,H,T,D] (half); 1: K proj -> RoPE (half);
// MODE 2: V proj (half); 3: O proj -> row-major float [M,N].
// ---------------------------------------------------------------------------
#define GSTR 40
#define TILE_B (128 * GSTR * 2)
#define GEMM_SMEM3 (3 * 2 * TILE_B)     // 61440 bytes

template <int MODE>
__global__ __launch_bounds__(256)
void gemm_f16(const __half* __restrict__ A, const __half* __restrict__ W,
              __half* __restrict__ out, float* __restrict__ outf, int N)
{
    extern __shared__ __align__(16) char smem[];
    const uint32_t sb = smem_u32(smem);

    const int tid = threadIdx.x;
    const int lane = tid & 31;
    const int wid = tid >> 5;
    const int wm = wid >> 2;
    const int wn = wid & 3;
    const int m0 = blockIdx.y * 128, n0 = blockIdx.x * 128;

    const int NTOT = K_DIM / 32;      // 64

    auto load_chunk = [&](int c) {
        int k0 = c * 32;
        uint32_t st = sb + (uint32_t)(c % 3) * (2 * TILE_B);
        const __half* As = A + (size_t)m0 * K_DIM + k0;
        const __half* Bs = W + (size_t)n0 * K_DIM + k0;
#pragma unroll
        for (int i = 0; i < 4; i++) {
            int idx = tid + i * 256;
            int rem = idx & 511;
            int r = rem >> 2, c4 = rem & 3;
            const __half* src = (idx < 512)
                ? (As + (size_t)r * K_DIM + c4 * 8)
                : (Bs + (size_t)r * K_DIM + c4 * 8);
            uint32_t dst = st + (uint32_t)((idx < 512) ? 0 : TILE_B)
                         + (uint32_t)(r * (GSTR * 2) + c4 * 16);
            cp_async16(dst, src);
        }
        cp_commit();
    };

    float acc[4][4][4];
#pragma unroll
    for (int mi = 0; mi < 4; mi++)
#pragma unroll
        for (int nf = 0; nf < 4; nf++)
#pragma unroll
            for (int e = 0; e < 4; e++) acc[mi][nf][e] = 0.f;

    const int a_row = lane & 15;
    const int a_col8 = (lane >> 4) * 8;
    const int b_row = (lane & 7) + ((lane & 16) >> 1);
    const int b_col8 = (lane & 8);

    load_chunk(0);
    load_chunk(1);

    for (int c = 0; c < NTOT; c++) {
        if (c + 2 < NTOT) cp_wait1();   // group c complete (c+1 may stay in flight)
        else              cp_wait0();   // tail: drain everything
        __syncthreads();                // buffer c visible; all warps past compute(c-1)
        if (c + 2 < NTOT) load_chunk(c + 2);   // overwrites buffer of chunk c-1 (safe)

        uint32_t st = sb + (uint32_t)(c % 3) * (2 * TILE_B);
        uint32_t aBase = st;
        uint32_t bBase = st + TILE_B;

#pragma unroll
        for (int s = 0; s < 2; s++) {
            uint32_t a[4][4];
#pragma unroll
            for (int mi = 0; mi < 4; mi++) {
                uint32_t addr = aBase + (uint32_t)(
                    (wm * 64 + mi * 16 + a_row) * (GSTR * 2) + (s * 16 + a_col8) * 2);
                ldsm4(a[mi][0], a[mi][1], a[mi][2], a[mi][3], addr);
            }
            uint32_t b[2][4];
#pragma unroll
            for (int nj = 0; nj < 2; nj++) {
                uint32_t addr = bBase + (uint32_t)(
                    (wn * 32 + nj * 16 + b_row) * (GSTR * 2) + (s * 16 + b_col8) * 2);
                ldsm4(b[nj][0], b[nj][1], b[nj][2], b[nj][3], addr);
            }
#pragma unroll
            for (int mi = 0; mi < 4; mi++)
#pragma unroll
                for (int nf = 0; nf < 4; nf++)
                    mma_f16(acc[mi][nf], a[mi],
                            b[nf >> 1][(nf & 1) * 2], b[nf >> 1][(nf & 1) * 2 + 1]);
        }
    }

    // epilogue: (e,o) adjacent col pair per acc half
#pragma unroll
    for (int mi = 0; mi < 4; mi++) {
        int r_loc = wm * 64 + mi * 16 + (lane >> 2);
#pragma unroll
        for (int half = 0; half < 2; half++) {
            int mr = m0 + r_loc + half * 8;
            int bb = mr >> 11;
            int t  = mr & (T_DIM - 1);
#pragma unroll
            for (int nf = 0; nf < 4; nf++) {
                int n = n0 + wn * 32 + nf * 8 + (lane & 3) * 2;
                float e = acc[mi][nf][half * 2];
                float o = acc[mi][nf][half * 2 + 1];
                if (MODE == 3) {
                    *(float2*)&outf[(size_t)mr * N + n] = make_float2(e, o);
                } else {
                    int hh = n >> 7, d = n & (HD - 1);
                    if (MODE == 2) {
                        *(__half2*)&out[(((size_t)bb * N_KV + hh) * T_DIM + t) * HD + d]
                            = __floats2half2_rn(e, o);
                    } else {
                        float cs = g_cos[t * 64 + (d >> 1)];
                        float sn = g_sin[t * 64 + (d >> 1)];
                        float oe = e * cs - o * sn;
                        float oo = e * sn + o * cs;
                        size_t idx;
                        if (MODE == 0) {
                            oe *= QK_SCALE; oo *= QK_SCALE;
                            idx = (((size_t)bb * N_HEAD + hh) * T_DIM + t) * HD + d;
                        } else {
                            idx = (((size_t)bb * N_KV + hh) * T_DIM + t) * HD + d;
                        }
                        *(__half2*)&out[idx] = __floats2half2_rn(oe, oo);
                    }
                }
            }
        }
    }
}

// ---------------------------------------------------------------------------
// fp16 tensor-core flash attention (FA2).
// BQ=128, BK=64, 256 threads = 8 warps; warp owns 16 q-rows x full tile.
// LPT schedule: qt = gridDim.x-1-blockIdx.x (heaviest CTAs first).
// ONE __syncthreads per tile; load(kt+1) issued after it, overlapping compute.
// Smem row stride 272B (128 halves + 8 pad) -> conflict-free ldsm.
// ---------------------------------------------------------------------------
#define FSTR 136                      // halves per row
#define FQ_B (128 * FSTR * 2)         // 34816
#define FKV_B (64 * FSTR * 2)         // 17408
#define FL_SMEM (FQ_B + 2 * 2 * FKV_B)  // 104448

__global__ __launch_bounds__(256, 1)
void flash_tc(const int* __restrict__ amask, __half* __restrict__ oh)
{
    extern __shared__ __align__(16) char smem[];
    const uint32_t sb = smem_u32(smem);
    __shared__ uint32_t s_ms[2][2];

    const int tid = threadIdx.x;
    const int lane = tid & 31;
    const int wid = tid >> 5;
    const int qt = gridDim.x - 1 - blockIdx.x;   // LPT: heavy tiles first
    const int h  = blockIdx.y;
    const int b  = blockIdx.z;
    const int kvh = h & (N_KV - 1);

    const __half* qb = g_qh + (((size_t)b * N_HEAD + h) * T_DIM + qt * 128) * HD;
    const __half* kb = g_kh + (((size_t)b * N_KV + kvh) * T_DIM) * HD;
    const __half* vb = g_vh + (((size_t)b * N_KV + kvh) * T_DIM) * HD;

    // ---- stage Q tile ----
#pragma unroll
    for (int i = 0; i < 8; i++) {
        int idx = tid + i * 256;          // 0..2047
        int r = idx >> 4, c16 = idx & 15;
        cp_async16(sb + (uint32_t)(r * (FSTR * 2) + c16 * 16),
                   qb + (size_t)r * HD + c16 * 8);
    }
    cp_commit();

    auto load_tile = [&](int c) {
        uint32_t st = sb + FQ_B + (uint32_t)(c & 1) * (2 * FKV_B);
        const __half* ks = kb + (size_t)c * 64 * HD;
        const __half* vs = vb + (size_t)c * 64 * HD;
#pragma unroll
        for (int i = 0; i < 8; i++) {
            int idx = tid + i * 256;      // 0..2047
            int rem = idx & 1023;
            int r = rem >> 4, c16 = rem & 15;
            const __half* src = (idx < 1024) ? (ks + (size_t)r * HD + c16 * 8)
                                             : (vs + (size_t)r * HD + c16 * 8);
            uint32_t dst = st + (uint32_t)((idx < 1024) ? 0 : FKV_B)
                         + (uint32_t)(r * (FSTR * 2) + c16 * 16);
            cp_async16(dst, src);
        }
        cp_commit();
        if (tid < 64) {
            int v = amask[b * T_DIM + c * 64 + tid];
            uint32_t bal = __ballot_sync(0xffffffffu, v != 0);
            if ((tid & 31) == 0) s_ms[c & 1][tid >> 5] = bal;
        }
    };

    load_tile(0);
    cp_wait0();
    __syncthreads();

    // ---- Q fragments (resident) ----
    uint32_t qa[8][4];
    {
        const int a_row = lane & 15;
        const int a_col8 = (lane >> 4) * 8;
#pragma unroll
        for (int s = 0; s < 8; s++) {
            uint32_t addr = sb + (uint32_t)(
                (wid * 16 + a_row) * (FSTR * 2) + (s * 16 + a_col8) * 2);
            ldsm4(qa[s][0], qa[s][1], qa[s][2], qa[s][3], addr);
        }
    }

    float o[16][4];
#pragma unroll
    for (int nf = 0; nf < 16; nf++)
#pragma unroll
        for (int e = 0; e < 4; e++) o[nf][e] = 0.f;
    float m_i[2] = {-1e30f, -1e30f};
    float l_i[2] = {0.f, 0.f};

    const int b_row = (lane & 7) + ((lane & 16) >> 1);
    const int b_col8 = (lane & 8);
    const int row_in_warp = lane >> 2;
    const int qg_base = qt * 128 + wid * 16 + row_in_warp;   // rows: +0 and +8

    const int nkt = 2 * qt + 2;
    for (int kt = 0; kt < nkt; kt++) {
        cp_wait0();          // tile kt fully resident
        __syncthreads();     // visible to all; all warps past reads of tile kt-1
        if (kt + 1 < nkt) load_tile(kt + 1);   // overwrites kt-1's buffer (safe)

        uint32_t kBase = sb + FQ_B + (uint32_t)(kt & 1) * (2 * FKV_B);
        uint32_t vBase = kBase + FKV_B;

        // ---- S = Q @ K^T : warp computes 16 x 64 ----
        float s[8][4];
#pragma unroll
        for (int nb = 0; nb < 8; nb++)
#pragma unroll
            for (int e = 0; e < 4; e++) s[nb][e] = 0.f;

#pragma unroll
        for (int ks = 0; ks < 8; ks++) {
            uint32_t bb[4][4];
#pragma unroll
            for (int nb2 = 0; nb2 < 4; nb2++) {
                uint32_t addr = kBase + (uint32_t)(
                    (nb2 * 16 + b_row) * (FSTR * 2) + (ks * 16 + b_col8) * 2);
                ldsm4(bb[nb2][0], bb[nb2][1], bb[nb2][2], bb[nb2][3], addr);
            }
#pragma unroll
            for (int nb2 = 0; nb2 < 4; nb2++) {
                mma_f16(s[2 * nb2],     qa[ks], bb[nb2][0], bb[nb2][1]);
                mma_f16(s[2 * nb2 + 1], qa[ks], bb[nb2][2], bb[nb2][3]);
            }
        }

        // ---- mask ----
        const uint32_t w0 = s_ms[kt & 1][0], w1 = s_ms[kt & 1][1];
        const bool diag = (kt >= 2 * qt);
        const bool full_pad = (w0 == 0xffffffffu) && (w1 == 0xffffffffu);
        if (diag || !full_pad) {
#pragma unroll
            for (int nb = 0; nb < 8; nb++)
#pragma unroll
                for (int e = 0; e < 4; e++) {
                    int col = nb * 8 + (lane & 3) * 2 + (e & 1);
                    bool ok = ((col < 32 ? (w0 >> col) : (w1 >> (col - 32))) & 1u) != 0u;
                    if (diag)
                        ok = ok && (kt * 64 + col <= qg_base + (e >> 1) * 8);
                    if (!ok) s[nb][e] = -1e30f;
                }
        }

        // ---- online softmax (rows r and r+8 per thread) ----
        float mx[2] = {-1e30f, -1e30f};
#pragma unroll
        for (int nb = 0; nb < 8; nb++)
#pragma unroll
            for (int e = 0; e < 4; e++) mx[e >> 1] = fmaxf(mx[e >> 1], s[nb][e]);
#pragma unroll
        for (int i = 0; i < 2; i++) {
            mx[i] = fmaxf(mx[i], __shfl_xor_sync(0xffffffffu, mx[i], 1));
            mx[i] = fmaxf(mx[i], __shfl_xor_sync(0xffffffffu, mx[i], 2));
        }
        float alpha[2], rs[2] = {0.f, 0.f};
#pragma unroll
        for (int i = 0; i < 2; i++) {
            float mn = fmaxf(m_i[i], mx[i]);
            alpha[i] = exp2p((m_i[i] - mn) * LOG2E);
            m_i[i] = mn;
        }
#pragma unroll
        for (int nb = 0; nb < 8; nb++)
#pragma unroll
            for (int e = 0; e < 4; e++) {
                float p = exp2p((s[nb][e] - m_i[e >> 1]) * LOG2E);
                s[nb][e] = p;
                rs[e >> 1] += p;
            }
#pragma unroll
        for (int i = 0; i < 2; i++) {
            rs[i] += __shfl_xor_sync(0xffffffffu, rs[i], 1);
            rs[i] += __shfl_xor_sync(0xffffffffu, rs[i], 2);
            l_i[i] = l_i[i] * alpha[i] + rs[i];
        }

        // ---- O *= alpha ----
#pragma unroll
        for (int nf = 0; nf < 16; nf++) {
            o[nf][0] *= alpha[0]; o[nf][1] *= alpha[0];
            o[nf][2] *= alpha[1]; o[nf][3] *= alpha[1];
        }

        // ---- O += P @ V ----
#pragma unroll
        for (int kb = 0; kb < 4; kb++) {
            uint32_t pa[4];
            pa[0] = pack_h2(s[2 * kb][0], s[2 * kb][1]);
            pa[1] = pack_h2(s[2 * kb][2], s[2 * kb][3]);
            pa[2] = pack_h2(s[2 * kb + 1][0], s[2 * kb + 1][1]);
            pa[3] = pack_h2(s[2 * kb + 1][2], s[2 * kb + 1][3]);
#pragma unroll
            for (int nd2 = 0; nd2 < 8; nd2++) {
                uint32_t v0, v1, v2, v3;
                uint32_t addr = vBase + (uint32_t)(
                    (kb * 16 + (lane & 15)) * (FSTR * 2)
                    + (nd2 * 16 + (lane >> 4) * 8) * 2);
                ldsm4t(v0, v1, v2, v3, addr);
                mma_f16(o[2 * nd2],     pa, v0, v1);
                mma_f16(o[2 * nd2 + 1], pa, v2, v3);
            }
        }
    }

    // ---- epilogue: fp16 A for the O-projection ----
    float inv[2] = {1.f / l_i[0], 1.f / l_i[1]};
#pragma unroll
    for (int half = 0; half < 2; half++) {
        size_t row = (size_t)b * T_DIM + qt * 128 + wid * 16 + row_in_warp + half * 8;
#pragma unroll
        for (int nf = 0; nf < 16; nf++) {
            int cc = h * HD + nf * 8 + (lane & 3) * 2;
            *(__half2*)&oh[row * C_DIM + cc] = __floats2half2_rn(
                o[nf][half * 2] * inv[half], o[nf][half * 2 + 1] * inv[half]);
        }
    }
}

// ---------------------------------------------------------------------------
// Launch
// ---------------------------------------------------------------------------
extern "C" void kernel_launch(void* const* d_in, const int* in_sizes, int n_in,
                              void* d_out, int out_size)
{
    const float* x    = (const float*)d_in[0];
    const float* rope = (const float*)d_in[1];
    const int*   am   = (const int*)  d_in[2];
    const float* Wq   = (const float*)d_in[3];
    const float* Wk   = (const float*)d_in[4];
    const float* Wv   = (const float*)d_in[5];
    const float* Wo   = (const float*)d_in[6];
    float* out = (float*)d_out;

    __half *xh, *wq16, *wk16, *wv16, *wo16, *qh, *kh, *vh, *ah;
    cudaGetSymbolAddress((void**)&xh, g_xh);
    cudaGetSymbolAddress((void**)&wq16, g_wq16);
    cudaGetSymbolAddress((void**)&wk16, g_wk16);
    cudaGetSymbolAddress((void**)&wv16, g_wv16);
    cudaGetSymbolAddress((void**)&wo16, g_wo16);
    cudaGetSymbolAddress((void**)&qh, g_qh);
    cudaGetSymbolAddress((void**)&kh, g_kh);
    cudaGetSymbolAddress((void**)&vh, g_vh);
    cudaGetSymbolAddress((void**)&ah, g_ah);

    cudaFuncSetAttribute(gemm_f16<0>, cudaFuncAttributeMaxDynamicSharedMemorySize, GEMM_SMEM3);
    cudaFuncSetAttribute(gemm_f16<1>, cudaFuncAttributeMaxDynamicSharedMemorySize, GEMM_SMEM3);
    cudaFuncSetAttribute(gemm_f16<2>, cudaFuncAttributeMaxDynamicSharedMemorySize, GEMM_SMEM3);
    cudaFuncSetAttribute(gemm_f16<3>, cudaFuncAttributeMaxDynamicSharedMemorySize, GEMM_SMEM3);
    cudaFuncSetAttribute(flash_tc, cudaFuncAttributeMaxDynamicSharedMemorySize, FL_SMEM);

    // prep
    rope_tables_kernel<<<(T_DIM * 64 + 255) / 256, 256>>>(rope);
    to_f16<<<(M_TOT * K_DIM / 8 + 255) / 256, 256>>>(x, xh, M_TOT * K_DIM / 8);
    to_f16<<<(C_DIM * K_DIM / 8 + 255) / 256, 256>>>(Wq, wq16, C_DIM * K_DIM / 8);
    to_f16<<<(NKV_C * K_DIM / 8 + 255) / 256, 256>>>(Wk, wk16, NKV_C * K_DIM / 8);
    to_f16<<<(NKV_C * K_DIM / 8 + 255) / 256, 256>>>(Wv, wv16, NKV_C * K_DIM / 8);
    to_f16<<<(C_DIM * K_DIM / 8 + 255) / 256, 256>>>(Wo, wo16, C_DIM * K_DIM / 8);

    // projections (fp16 mma, 3-stage pipeline)
    gemm_f16<0><<<dim3(C_DIM / 128, M_TOT / 128), 256, GEMM_SMEM3>>>(xh, wq16, qh, nullptr, C_DIM);
    gemm_f16<1><<<dim3(NKV_C / 128, M_TOT / 128), 256, GEMM_SMEM3>>>(xh, wk16, kh, nullptr, NKV_C);
    gemm_f16<2><<<dim3(NKV_C / 128, M_TOT / 128), 256, GEMM_SMEM3>>>(xh, wv16, vh, nullptr, NKV_C);

    // attention (fp16 tensor cores, LPT-scheduled)
    flash_tc<<<dim3(T_DIM / 128, N_HEAD, B_DIM), 256, FL_SMEM>>>(am, ah);

    // O projection (fp16 single pass, fp32 accum)
    gemm_f16<3><<<dim3(C_DIM / 128, M_TOT / 128), 256, GEMM_SMEM3>>>(ah, wo16, nullptr, out, C_DIM);
}

// round 14
// speedup vs baseline: 8.8467x; 1.0102x over previous
#include <cuda_runtime.h>
#include <cuda_bf16.h>
#include <cuda_fp16.h>
#include <math.h>
#include <cstdint>

// ---------------------------------------------------------------------------
#define B_DIM 4
#define T_DIM 2048
#define C_DIM 2048
#define N_HEAD 16
#define N_KV 4
#define HD 128
#define M_TOT (B_DIM * T_DIM)           // 8192
#define K_DIM 2048
#define NKV_C (N_KV * HD)               // 512
#define NQKV (C_DIM + 2 * NKV_C)        // 3072
#define QK_SCALE 0.08838834764831845f   // 1/sqrt(128)
#define LOG2E 1.4426950408889634f

// ---------------------------------------------------------------------------
// Scratch (static device globals)
// ---------------------------------------------------------------------------
__device__ __half g_xh[(size_t)M_TOT * K_DIM];
__device__ __half g_wqkv[(size_t)NQKV * K_DIM];               // [Wq;Wk;Wv]
__device__ __half g_wo16[(size_t)C_DIM * K_DIM];
__device__ __half g_qh[(size_t)B_DIM * N_HEAD * T_DIM * HD];  // [B,H,T,D]
__device__ __half g_kh[(size_t)B_DIM * N_KV * T_DIM * HD];
__device__ __half g_vh[(size_t)B_DIM * N_KV * T_DIM * HD];
__device__ __half g_ah[(size_t)M_TOT * C_DIM];                // attn out fp16
__device__ float g_cos[(size_t)T_DIM * 64];
__device__ float g_sin[(size_t)T_DIM * 64];

// ---------------------------------------------------------------------------
// Helpers (sm_100-safe)
// ---------------------------------------------------------------------------
__device__ __forceinline__ uint32_t smem_u32(const void* p) {
    uint32_t a;
    asm("{ .reg .u64 t; cvta.to.shared.u64 t, %1; cvt.u32.u64 %0, t; }"
        : "=r"(a) : "l"(p));
    return a;
}
__device__ __forceinline__ void cp_async16(uint32_t dst, const void* src) {
    asm volatile("cp.async.cg.shared.global [%0], [%1], 16;" :: "r"(dst), "l"(src));
}
__device__ __forceinline__ void cp_commit() {
    asm volatile("cp.async.commit_group;" ::: "memory");
}
__device__ __forceinline__ void cp_wait1() {
    asm volatile("cp.async.wait_group 1;" ::: "memory");
}
__device__ __forceinline__ void cp_wait0() {
    asm volatile("cp.async.wait_group 0;" ::: "memory");
}
__device__ __forceinline__ void ldsm4(uint32_t& r0, uint32_t& r1, uint32_t& r2,
                                      uint32_t& r3, uint32_t addr) {
    asm volatile("ldmatrix.sync.aligned.m8n8.x4.shared.b16 {%0,%1,%2,%3}, [%4];"
                 : "=r"(r0), "=r"(r1), "=r"(r2), "=r"(r3) : "r"(addr));
}
__device__ __forceinline__ void ldsm4t(uint32_t& r0, uint32_t& r1, uint32_t& r2,
                                       uint32_t& r3, uint32_t addr) {
    asm volatile("ldmatrix.sync.aligned.m8n8.x4.trans.shared.b16 {%0,%1,%2,%3}, [%4];"
                 : "=r"(r0), "=r"(r1), "=r"(r2), "=r"(r3) : "r"(addr));
}
__device__ __forceinline__ void mma_f16(float* d, const uint32_t* a,
                                        uint32_t b0, uint32_t b1) {
    asm volatile(
        "mma.sync.aligned.m16n8k16.row.col.f32.f16.f16.f32 "
        "{%0,%1,%2,%3}, {%4,%5,%6,%7}, {%8,%9}, {%0,%1,%2,%3};"
        : "+f"(d[0]), "+f"(d[1]), "+f"(d[2]), "+f"(d[3])
        : "r"(a[0]), "r"(a[1]), "r"(a[2]), "r"(a[3]), "r"(b0), "r"(b1));
}
// fast exp2: degree-5 poly, FFMA pipe only (no MUFU)
__device__ __forceinline__ float exp2p(float x) {
    x = fmaxf(x, -126.f);
    float t = rintf(x);
    float f = x - t;
    float p = 0.0013333558f;
    p = fmaf(p, f, 0.0096181291f);
    p = fmaf(p, f, 0.0555041087f);
    p = fmaf(p, f, 0.2402265070f);
    p = fmaf(p, f, 0.6931471806f);
    p = fmaf(p, f, 1.0f);
    return __int_as_float(__float_as_int(p) + (((int)t) << 23));
}
__device__ __forceinline__ uint32_t pack_h2(float x, float y) {
    __half2 h = __floats2half2_rn(x, y);
    return *(uint32_t*)&h;
}
__device__ __forceinline__ uint4 cvt8_f16(const float* src) {
    float4 a = ((const float4*)src)[0], b = ((const float4*)src)[1];
    __half2 h0 = __floats2half2_rn(a.x, a.y);
    __half2 h1 = __floats2half2_rn(a.z, a.w);
    __half2 h2 = __floats2half2_rn(b.x, b.y);
    __half2 h3 = __floats2half2_rn(b.z, b.w);
    uint4 u;
    u.x = *(uint32_t*)&h0; u.y = *(uint32_t*)&h1;
    u.z = *(uint32_t*)&h2; u.w = *(uint32_t*)&h3;
    return u;
}

// ---------------------------------------------------------------------------
// Prep kernels
// ---------------------------------------------------------------------------
__global__ void rope_tables_kernel(const float* __restrict__ rope) {
    int i = blockIdx.x * 256 + threadIdx.x;
    if (i < T_DIM * 64) {
        float sn, cs;
        sincosf(rope[i], &sn, &cs);
        g_sin[i] = sn; g_cos[i] = cs;
    }
}

__global__ void to_f16(const float* __restrict__ src, __half* __restrict__ dst, int n8) {
    int i = blockIdx.x * 256 + threadIdx.x;
    if (i >= n8) return;
    ((uint4*)dst)[i] = cvt8_f16(src + (size_t)i * 8);
}

// Converts Wq,Wk,Wv -> g_wqkv (concatenated rows) and Wo -> g_wo16, one launch.
__global__ void conv_weights(const float* __restrict__ Wq, const float* __restrict__ Wk,
                             const float* __restrict__ Wv, const float* __restrict__ Wo) {
    const int NW1 = (NQKV * K_DIM) / 8;     // 786432
    const int NW2 = (C_DIM * K_DIM) / 8;    // 524288
    int i = blockIdx.x * 256 + threadIdx.x;
    if (i >= NW1 + NW2) return;
    if (i < NW1) {
        size_t e8 = (size_t)i * 8;
        int r = (int)(e8 >> 11);            // row (K_DIM = 2048)
        int cc = (int)(e8 & 2047);
        const float* src;
        if (r < C_DIM)              src = Wq + (size_t)r * K_DIM + cc;
        else if (r < C_DIM + NKV_C) src = Wk + (size_t)(r - C_DIM) * K_DIM + cc;
        else                        src = Wv + (size_t)(r - C_DIM - NKV_C) * K_DIM + cc;
        ((uint4*)g_wqkv)[i] = cvt8_f16(src);
    } else {
        size_t e8 = (size_t)(i - NW1) * 8;
        ((uint4*)g_wo16)[i - NW1] = cvt8_f16(Wo + e8);
    }
}

// ---------------------------------------------------------------------------
// fp16 single-pass NT GEMM: out = A[M,K] @ W[N,K]^T, fp32 accum.
// 128x128 tile/CTA, BK=32, 256 threads, warp tile 64x32.
// 3-stage cp.async pipeline (dynamic smem, 60KB), ONE __syncthreads per chunk.
// MODE 4: merged QKV -> writes g_qh (RoPE+scale) / g_kh (RoPE) / g_vh by n-region.
// MODE 3: O proj -> row-major float [M,N].
// ---------------------------------------------------------------------------
#define GSTR 40
#define TILE_B (128 * GSTR * 2)
#define GEMM_SMEM3 (3 * 2 * TILE_B)     // 61440 bytes

template <int MODE>
__global__ __launch_bounds__(256)
void gemm_f16(const __half* __restrict__ A, const __half* __restrict__ W,
              float* __restrict__ outf, int N)
{
    extern __shared__ __align__(16) char smem[];
    const uint32_t sb = smem_u32(smem);

    const int tid = threadIdx.x;
    const int lane = tid & 31;
    const int wid = tid >> 5;
    const int wm = wid >> 2;
    const int wn = wid & 3;
    const int m0 = blockIdx.y * 128, n0 = blockIdx.x * 128;

    const int NTOT = K_DIM / 32;      // 64

    auto load_chunk = [&](int c) {
        int k0 = c * 32;
        uint32_t st = sb + (uint32_t)(c % 3) * (2 * TILE_B);
        const __half* As = A + (size_t)m0 * K_DIM + k0;
        const __half* Bs = W + (size_t)n0 * K_DIM + k0;
#pragma unroll
        for (int i = 0; i < 4; i++) {
            int idx = tid + i * 256;
            int rem = idx & 511;
            int r = rem >> 2, c4 = rem & 3;
            const __half* src = (idx < 512)
                ? (As + (size_t)r * K_DIM + c4 * 8)
                : (Bs + (size_t)r * K_DIM + c4 * 8);
            uint32_t dst = st + (uint32_t)((idx < 512) ? 0 : TILE_B)
                         + (uint32_t)(r * (GSTR * 2) + c4 * 16);
            cp_async16(dst, src);
        }
        cp_commit();
    };

    float acc[4][4][4];
#pragma unroll
    for (int mi = 0; mi < 4; mi++)
#pragma unroll
        for (int nf = 0; nf < 4; nf++)
#pragma unroll
            for (int e = 0; e < 4; e++) acc[mi][nf][e] = 0.f;

    const int a_row = lane & 15;
    const int a_col8 = (lane >> 4) * 8;
    const int b_row = (lane & 7) + ((lane & 16) >> 1);
    const int b_col8 = (lane & 8);

    load_chunk(0);
    load_chunk(1);

    for (int c = 0; c < NTOT; c++) {
        if (c + 2 < NTOT) cp_wait1();   // group c complete (c+1 may stay in flight)
        else              cp_wait0();   // tail: drain everything
        __syncthreads();                // buffer c visible; all warps past compute(c-1)
        if (c + 2 < NTOT) load_chunk(c + 2);   // overwrites buffer of chunk c-1 (safe)

        uint32_t st = sb + (uint32_t)(c % 3) * (2 * TILE_B);
        uint32_t aBase = st;
        uint32_t bBase = st + TILE_B;

#pragma unroll
        for (int s = 0; s < 2; s++) {
            uint32_t a[4][4];
#pragma unroll
            for (int mi = 0; mi < 4; mi++) {
                uint32_t addr = aBase + (uint32_t)(
                    (wm * 64 + mi * 16 + a_row) * (GSTR * 2) + (s * 16 + a_col8) * 2);
                ldsm4(a[mi][0], a[mi][1], a[mi][2], a[mi][3], addr);
            }
            uint32_t b[2][4];
#pragma unroll
            for (int nj = 0; nj < 2; nj++) {
                uint32_t addr = bBase + (uint32_t)(
                    (wn * 32 + nj * 16 + b_row) * (GSTR * 2) + (s * 16 + b_col8) * 2);
                ldsm4(b[nj][0], b[nj][1], b[nj][2], b[nj][3], addr);
            }
#pragma unroll
            for (int mi = 0; mi < 4; mi++)
#pragma unroll
                for (int nf = 0; nf < 4; nf++)
                    mma_f16(acc[mi][nf], a[mi],
                            b[nf >> 1][(nf & 1) * 2], b[nf >> 1][(nf & 1) * 2 + 1]);
        }
    }

    // epilogue: (e,o) adjacent col pair per acc half
#pragma unroll
    for (int mi = 0; mi < 4; mi++) {
        int r_loc = wm * 64 + mi * 16 + (lane >> 2);
#pragma unroll
        for (int half = 0; half < 2; half++) {
            int mr = m0 + r_loc + half * 8;
            int bb = mr >> 11;
            int t  = mr & (T_DIM - 1);
#pragma unroll
            for (int nf = 0; nf < 4; nf++) {
                int n = n0 + wn * 32 + nf * 8 + (lane & 3) * 2;
                float e = acc[mi][nf][half * 2];
                float o = acc[mi][nf][half * 2 + 1];
                if (MODE == 3) {
                    *(float2*)&outf[(size_t)mr * N + n] = make_float2(e, o);
                } else {
                    // MODE 4: merged QKV; region uniform per CTA (128-aligned)
                    if (n < C_DIM) {
                        int hh = n >> 7, d = n & (HD - 1);
                        float cs = g_cos[t * 64 + (d >> 1)];
                        float sn = g_sin[t * 64 + (d >> 1)];
                        float oe = (e * cs - o * sn) * QK_SCALE;
                        float oo = (e * sn + o * cs) * QK_SCALE;
                        *(__half2*)&g_qh[(((size_t)bb * N_HEAD + hh) * T_DIM + t) * HD + d]
                            = __floats2half2_rn(oe, oo);
                    } else if (n < C_DIM + NKV_C) {
                        int nk = n - C_DIM;
                        int hh = nk >> 7, d = nk & (HD - 1);
                        float cs = g_cos[t * 64 + (d >> 1)];
                        float sn = g_sin[t * 64 + (d >> 1)];
                        float oe = e * cs - o * sn;
                        float oo = e * sn + o * cs;
                        *(__half2*)&g_kh[(((size_t)bb * N_KV + hh) * T_DIM + t) * HD + d]
                            = __floats2half2_rn(oe, oo);
                    } else {
                        int nv = n - C_DIM - NKV_C;
                        int hh = nv >> 7, d = nv & (HD - 1);
                        *(__half2*)&g_vh[(((size_t)bb * N_KV + hh) * T_DIM + t) * HD + d]
                            = __floats2half2_rn(e, o);
                    }
                }
            }
        }
    }
}

// ---------------------------------------------------------------------------
// fp16 tensor-core flash attention (FA2).
// BQ=128, BK=64, 256 threads = 8 warps; warp owns 16 q-rows x full tile.
// LPT schedule: qt = gridDim.x-1-blockIdx.x (heaviest CTAs first).
// ONE __syncthreads per tile; load(kt+1) issued after it, overlapping compute.
// Smem row stride 272B (128 halves + 8 pad) -> conflict-free ldsm.
// ---------------------------------------------------------------------------
#define FSTR 136                      // halves per row
#define FQ_B (128 * FSTR * 2)         // 34816
#define FKV_B (64 * FSTR * 2)         // 17408
#define FL_SMEM (FQ_B + 2 * 2 * FKV_B)  // 104448

__global__ __launch_bounds__(256, 1)
void flash_tc(const int* __restrict__ amask, __half* __restrict__ oh)
{
    extern __shared__ __align__(16) char smem[];
    const uint32_t sb = smem_u32(smem);
    __shared__ uint32_t s_ms[2][2];

    const int tid = threadIdx.x;
    const int lane = tid & 31;
    const int wid = tid >> 5;
    const int qt = gridDim.x - 1 - blockIdx.x;   // LPT: heavy tiles first
    const int h  = blockIdx.y;
    const int b  = blockIdx.z;
    const int kvh = h & (N_KV - 1);

    const __half* qb = g_qh + (((size_t)b * N_HEAD + h) * T_DIM + qt * 128) * HD;
    const __half* kb = g_kh + (((size_t)b * N_KV + kvh) * T_DIM) * HD;
    const __half* vb = g_vh + (((size_t)b * N_KV + kvh) * T_DIM) * HD;

    // ---- stage Q tile ----
#pragma unroll
    for (int i = 0; i < 8; i++) {
        int idx = tid + i * 256;          // 0..2047
        int r = idx >> 4, c16 = idx & 15;
        cp_async16(sb + (uint32_t)(r * (FSTR * 2) + c16 * 16),
                   qb + (size_t)r * HD + c16 * 8);
    }
    cp_commit();

    auto load_tile = [&](int c) {
        uint32_t st = sb + FQ_B + (uint32_t)(c & 1) * (2 * FKV_B);
        const __half* ks = kb + (size_t)c * 64 * HD;
        const __half* vs = vb + (size_t)c * 64 * HD;
#pragma unroll
        for (int i = 0; i < 8; i++) {
            int idx = tid + i * 256;      // 0..2047
            int rem = idx & 1023;
            int r = rem >> 4, c16 = rem & 15;
            const __half* src = (idx < 1024) ? (ks + (size_t)r * HD + c16 * 8)
                                             : (vs + (size_t)r * HD + c16 * 8);
            uint32_t dst = st + (uint32_t)((idx < 1024) ? 0 : FKV_B)
                         + (uint32_t)(r * (FSTR * 2) + c16 * 16);
            cp_async16(dst, src);
        }
        cp_commit();
        if (tid < 64) {
            int v = amask[b * T_DIM + c * 64 + tid];
            uint32_t bal = __ballot_sync(0xffffffffu, v != 0);
            if ((tid & 31) == 0) s_ms[c & 1][tid >> 5] = bal;
        }
    };

    load_tile(0);
    cp_wait0();
    __syncthreads();

    // ---- Q fragments (resident) ----
    uint32_t qa[8][4];
    {
        const int a_row = lane & 15;
        const int a_col8 = (lane >> 4) * 8;
#pragma unroll
        for (int s = 0; s < 8; s++) {
            uint32_t addr = sb + (uint32_t)(
                (wid * 16 + a_row) * (FSTR * 2) + (s * 16 + a_col8) * 2);
            ldsm4(qa[s][0], qa[s][1], qa[s][2], qa[s][3], addr);
        }
    }

    float o[16][4];
#pragma unroll
    for (int nf = 0; nf < 16; nf++)
#pragma unroll
        for (int e = 0; e < 4; e++) o[nf][e] = 0.f;
    float m_i[2] = {-1e30f, -1e30f};
    float l_i[2] = {0.f, 0.f};

    const int b_row = (lane & 7) + ((lane & 16) >> 1);
    const int b_col8 = (lane & 8);
    const int row_in_warp = lane >> 2;
    const int qg_base = qt * 128 + wid * 16 + row_in_warp;   // rows: +0 and +8

    const int nkt = 2 * qt + 2;
    for (int kt = 0; kt < nkt; kt++) {
        cp_wait0();          // tile kt fully resident
        __syncthreads();     // visible to all; all warps past reads of tile kt-1
        if (kt + 1 < nkt) load_tile(kt + 1);   // overwrites kt-1's buffer (safe)

        uint32_t kBase = sb + FQ_B + (uint32_t)(kt & 1) * (2 * FKV_B);
        uint32_t vBase = kBase + FKV_B;

        // ---- S = Q @ K^T : warp computes 16 x 64 ----
        float s[8][4];
#pragma unroll
        for (int nb = 0; nb < 8; nb++)
#pragma unroll
            for (int e = 0; e < 4; e++) s[nb][e] = 0.f;

#pragma unroll
        for (int ks = 0; ks < 8; ks++) {
            uint32_t bb[4][4];
#pragma unroll
            for (int nb2 = 0; nb2 < 4; nb2++) {
                uint32_t addr = kBase + (uint32_t)(
                    (nb2 * 16 + b_row) * (FSTR * 2) + (ks * 16 + b_col8) * 2);
                ldsm4(bb[nb2][0], bb[nb2][1], bb[nb2][2], bb[nb2][3], addr);
            }
#pragma unroll
            for (int nb2 = 0; nb2 < 4; nb2++) {
                mma_f16(s[2 * nb2],     qa[ks], bb[nb2][0], bb[nb2][1]);
                mma_f16(s[2 * nb2 + 1], qa[ks], bb[nb2][2], bb[nb2][3]);
            }
        }

        // ---- mask ----
        const uint32_t w0 = s_ms[kt & 1][0], w1 = s_ms[kt & 1][1];
        const bool diag = (kt >= 2 * qt);
        const bool full_pad = (w0 == 0xffffffffu) && (w1 == 0xffffffffu);
        if (diag || !full_pad) {
#pragma unroll
            for (int nb = 0; nb < 8; nb++)
#pragma unroll
                for (int e = 0; e < 4; e++) {
                    int col = nb * 8 + (lane & 3) * 2 + (e & 1);
                    bool ok = ((col < 32 ? (w0 >> col) : (w1 >> (col - 32))) & 1u) != 0u;
                    if (diag)
                        ok = ok && (kt * 64 + col <= qg_base + (e >> 1) * 8);
                    if (!ok) s[nb][e] = -1e30f;
                }
        }

        // ---- online softmax (rows r and r+8 per thread) ----
        float mx[2] = {-1e30f, -1e30f};
#pragma unroll
        for (int nb = 0; nb < 8; nb++)
#pragma unroll
            for (int e = 0; e < 4; e++) mx[e >> 1] = fmaxf(mx[e >> 1], s[nb][e]);
#pragma unroll
        for (int i = 0; i < 2; i++) {
            mx[i] = fmaxf(mx[i], __shfl_xor_sync(0xffffffffu, mx[i], 1));
            mx[i] = fmaxf(mx[i], __shfl_xor_sync(0xffffffffu, mx[i], 2));
        }
        float alpha[2], rs[2] = {0.f, 0.f};
#pragma unroll
        for (int i = 0; i < 2; i++) {
            float mn = fmaxf(m_i[i], mx[i]);
            alpha[i] = exp2p((m_i[i] - mn) * LOG2E);
            m_i[i] = mn;
        }
#pragma unroll
        for (int nb = 0; nb < 8; nb++)
#pragma unroll
            for (int e = 0; e < 4; e++) {
                float p = exp2p((s[nb][e] - m_i[e >> 1]) * LOG2E);
                s[nb][e] = p;
                rs[e >> 1] += p;
            }
#pragma unroll
        for (int i = 0; i < 2; i++) {
            rs[i] += __shfl_xor_sync(0xffffffffu, rs[i], 1);
            rs[i] += __shfl_xor_sync(0xffffffffu, rs[i], 2);
            l_i[i] = l_i[i] * alpha[i] + rs[i];
        }

        // ---- O *= alpha ----
#pragma unroll
        for (int nf = 0; nf < 16; nf++) {
            o[nf][0] *= alpha[0]; o[nf][1] *= alpha[0];
            o[nf][2] *= alpha[1]; o[nf][3] *= alpha[1];
        }

        // ---- O += P @ V ----
#pragma unroll
        for (int kb = 0; kb < 4; kb++) {
            uint32_t pa[4];
            pa[0] = pack_h2(s[2 * kb][0], s[2 * kb][1]);
            pa[1] = pack_h2(s[2 * kb][2], s[2 * kb][3]);
            pa[2] = pack_h2(s[2 * kb + 1][0], s[2 * kb + 1][1]);
            pa[3] = pack_h2(s[2 * kb + 1][2], s[2 * kb + 1][3]);
#pragma unroll
            for (int nd2 = 0; nd2 < 8; nd2++) {
                uint32_t v0, v1, v2, v3;
                uint32_t addr = vBase + (uint32_t)(
                    (kb * 16 + (lane & 15)) * (FSTR * 2)
                    + (nd2 * 16 + (lane >> 4) * 8) * 2);
                ldsm4t(v0, v1, v2, v3, addr);
                mma_f16(o[2 * nd2],     pa, v0, v1);
                mma_f16(o[2 * nd2 + 1], pa, v2, v3);
            }
        }
    }

    // ---- epilogue: fp16 A for the O-projection ----
    float inv[2] = {1.f / l_i[0], 1.f / l_i[1]};
#pragma unroll
    for (int half = 0; half < 2; half++) {
        size_t row = (size_t)b * T_DIM + qt * 128 + wid * 16 + row_in_warp + half * 8;
#pragma unroll
        for (int nf = 0; nf < 16; nf++) {
            int cc = h * HD + nf * 8 + (lane & 3) * 2;
            *(__half2*)&oh[row * C_DIM + cc] = __floats2half2_rn(
                o[nf][half * 2] * inv[half], o[nf][half * 2 + 1] * inv[half]);
        }
    }
}

// ---------------------------------------------------------------------------
// Launch
// ---------------------------------------------------------------------------
extern "C" void kernel_launch(void* const* d_in, const int* in_sizes, int n_in,
                              void* d_out, int out_size)
{
    const float* x    = (const float*)d_in[0];
    const float* rope = (const float*)d_in[1];
    const int*   am   = (const int*)  d_in[2];
    const float* Wq   = (const float*)d_in[3];
    const float* Wk   = (const float*)d_in[4];
    const float* Wv   = (const float*)d_in[5];
    const float* Wo   = (const float*)d_in[6];
    float* out = (float*)d_out;

    __half *xh, *wqkv, *wo16, *ah;
    cudaGetSymbolAddress((void**)&xh, g_xh);
    cudaGetSymbolAddress((void**)&wqkv, g_wqkv);
    cudaGetSymbolAddress((void**)&wo16, g_wo16);
    cudaGetSymbolAddress((void**)&ah, g_ah);

    cudaFuncSetAttribute(gemm_f16<3>, cudaFuncAttributeMaxDynamicSharedMemorySize, GEMM_SMEM3);
    cudaFuncSetAttribute(gemm_f16<4>, cudaFuncAttributeMaxDynamicSharedMemorySize, GEMM_SMEM3);
    cudaFuncSetAttribute(flash_tc, cudaFuncAttributeMaxDynamicSharedMemorySize, FL_SMEM);

    // prep (launch indices 0..2)
    rope_tables_kernel<<<(T_DIM * 64 + 255) / 256, 256>>>(rope);
    conv_weights<<<((NQKV + C_DIM) * K_DIM / 8 + 255) / 256, 256>>>(Wq, Wk, Wv, Wo);
    to_f16<<<(M_TOT * K_DIM / 8 + 255) / 256, 256>>>(x, xh, M_TOT * K_DIM / 8);

    // merged QKV projection (index 3)
    gemm_f16<4><<<dim3(NQKV / 128, M_TOT / 128), 256, GEMM_SMEM3>>>(xh, wqkv, nullptr, NQKV);

    // attention (index 4)
    flash_tc<<<dim3(T_DIM / 128, N_HEAD, B_DIM), 256, FL_SMEM>>>(am, ah);

    // O projection (index 5 -- ncu -s 5 captures this GEMM)
    gemm_f16<3><<<dim3(C_DIM / 128, M_TOT / 128), 256, GEMM_SMEM3>>>(ah, wo16, out, C_DIM);
}